// round 11
// baseline (speedup 1.0000x reference)
#include <cuda_runtime.h>
#include <math.h>

// ---------------- problem constants ----------------
#define B_   8
#define T_   1024
#define C_   768
#define H_   12
#define HS_  64
#define E_   8
#define F_   3072
#define N_   (B_*T_)     // 8192 tokens
#define BH_  (B_*H_)     // 96
#define C3_  (3*C_)      // 2304

// ---------------- scratch (device globals; no allocation) ----------------
__device__ float g_h1  [N_*C_];
__device__ float g_qkv [N_*C3_];
__device__ float g_S   [(size_t)BH_*T_*T_];   // 402 MB scores/probs (in-place softmax)
__device__ float g_o   [N_*C_];
__device__ float g_h2  [N_*C_];
__device__ float g_mid1[N_*F_];
__device__ float g_mid2[N_*F_];
__device__ float g_Y   [N_*C_];
__device__ float g_Wqkv[C_*C3_];
__device__ int   g_cnt [E_];
__device__ int   g_tok [E_*N_];
__device__ float g_gw  [E_*N_];

// ---------------- helpers ----------------
__device__ __forceinline__ float gelu_f(float z) {
    return 0.5f * z * (1.0f + erff(z * 0.70710678118654752440f));
}

__device__ __forceinline__ unsigned f2tf32(float f) {
    unsigned r;
    asm("cvt.rna.tf32.f32 %0, %1;" : "=r"(r) : "f"(f));
    return r;
}

__device__ __forceinline__ void ldsm4(unsigned &r0, unsigned &r1, unsigned &r2, unsigned &r3,
                                      const unsigned* p) {
    unsigned addr = (unsigned)__cvta_generic_to_shared(p);
    asm volatile("ldmatrix.sync.aligned.m8n8.x4.shared.b16 {%0,%1,%2,%3}, [%4];"
        : "=r"(r0), "=r"(r1), "=r"(r2), "=r"(r3) : "r"(addr));
}

__device__ __forceinline__ void mma_tf32(float* c, const unsigned* a, const unsigned* b) {
    asm volatile("mma.sync.aligned.m16n8k8.row.col.f32.tf32.tf32.f32 "
        "{%0,%1,%2,%3}, {%4,%5,%6,%7}, {%8,%9}, {%0,%1,%2,%3};"
        : "+f"(c[0]), "+f"(c[1]), "+f"(c[2]), "+f"(c[3])
        : "r"(a[0]), "r"(a[1]), "r"(a[2]), "r"(a[3]), "r"(b[0]), "r"(b[1]));
}

// block-wide sum for 256 threads (8 warps)
__device__ __forceinline__ float blockReduceSum256(float v) {
    __shared__ float sh[8];
    int lane = threadIdx.x & 31, w = threadIdx.x >> 5;
    #pragma unroll
    for (int o = 16; o; o >>= 1) v += __shfl_down_sync(0xffffffffu, v, o);
    if (lane == 0) sh[w] = v;
    __syncthreads();
    float r;
    if (w == 0) {
        float t = (lane < 8) ? sh[lane] : 0.f;
        #pragma unroll
        for (int o = 4; o; o >>= 1) t += __shfl_down_sync(0xffffffffu, t, o);
        if (lane == 0) sh[0] = t;
    }
    __syncthreads();
    r = sh[0];
    __syncthreads();
    return r;
}

// ---------------- small setup kernels ----------------
__global__ void zero_cnt_kernel(int* cnt) {
    if (threadIdx.x < E_) cnt[threadIdx.x] = 0;
}

// pack wq,wk,wv (H,C,HS) -> Wqkv[C][3C] with col = which*C + h*HS + d
__global__ void pack_wqkv_kernel(const float* __restrict__ wq,
                                 const float* __restrict__ wk,
                                 const float* __restrict__ wv) {
    int idx = blockIdx.x * 256 + threadIdx.x;
    if (idx >= C_ * C3_) return;
    int c   = idx / C3_;
    int col = idx - c * C3_;
    int which = col / C_;
    int rem   = col - which * C_;
    int h = rem / HS_;
    int d = rem - h * HS_;
    const float* w = (which == 0) ? wq : ((which == 1) ? wk : wv);
    g_Wqkv[idx] = w[(h * C_ + c) * HS_ + d];
}

// LayerNorm over C=768 (one row per block, 256 threads x 3 elems)
__global__ __launch_bounds__(256) void ln_kernel(const float* __restrict__ in,
                                                 const float* __restrict__ g,
                                                 const float* __restrict__ b,
                                                 float* __restrict__ out) {
    int row = blockIdx.x;
    const float* p = in + (size_t)row * C_;
    int t = threadIdx.x;
    float x0 = p[t], x1 = p[t + 256], x2 = p[t + 512];
    float mean = blockReduceSum256(x0 + x1 + x2) * (1.0f / C_);
    float d0 = x0 - mean, d1 = x1 - mean, d2 = x2 - mean;
    float var = blockReduceSum256(d0*d0 + d1*d1 + d2*d2) * (1.0f / C_);
    float rstd = rsqrtf(var + 1e-5f);
    float* o = out + (size_t)row * C_;
    o[t]       = d0 * rstd * g[t]       + b[t];
    o[t + 256] = d1 * rstd * g[t + 256] + b[t + 256];
    o[t + 512] = d2 * rstd * g[t + 512] + b[t + 512];
}

// ---------------- tf32 tensor-core GEMM ----------------
// C[m,n] = act(A[m,:] @ B[:,n] + bias[n]) (+ resid[m,n])
// Block tile 128x128x16, 8 warps (2x4), warp tile 64x32 via mma.m16n8k8 tf32.
// GATHER: A row index from rows[m]; cntPtr (if non-null) overrides M.
// Requires Nn % 128 == 0, Kk % 16 == 0.
template<bool GATHER, int ACT, bool RESID>
__global__ __launch_bounds__(256) void tgemm_k(
    const float* __restrict__ A, int lda,
    const float* __restrict__ Bm,
    const float* __restrict__ bias,
    const float* __restrict__ resid,
    float* __restrict__ Cm, int ldc,
    int M, int Nn, int Kk,
    const int* __restrict__ rows,
    const int* __restrict__ cntPtr)
{
    if (cntPtr) M = *cntPtr;
    int m0 = blockIdx.y * 128;
    if (m0 >= M) return;
    int n0 = blockIdx.x * 128;

    __shared__ unsigned As[2][128][20];   // [row][k], pad 20 -> conflict-free ldsm
    __shared__ unsigned Bs[2][16][136];   // [k][n],  pad 136 -> conflict-free LDS
    __shared__ int rIdx[128];

    int tid = threadIdx.x;
    if (GATHER) {
        if (tid < 128) {
            int m = m0 + tid;
            rIdx[tid] = rows[(m < M) ? m : (M - 1)];
        }
        __syncthreads();
    }

    // ---- gmem load mapping ----
    // A: thread loads row (tid&127), two float4 at k-cols aCol and aCol+8
    int aRow = tid & 127;
    int aCol = (tid >> 7) * 4;   // 0 or 4
    int aSrcRow;
    if (GATHER) aSrcRow = rIdx[aRow];
    else { int gm = m0 + aRow; aSrcRow = (gm < M) ? gm : (M - 1); }
    const float* aPtr = A + (size_t)aSrcRow * lda;
    // B: thread loads k-row (tid>>4), two float4 at n-cols bN and bN+64
    int bK = tid >> 4;
    int bN = (tid & 15) * 4;
    const float* bPtr = Bm + (size_t)bK * Nn + n0;

    float4 aV0, aV1, bV0, bV1;

    // ---- warp / fragment mapping ----
    int wid = tid >> 5, lane = tid & 31;
    int warpM = (wid >> 2) * 64;     // 0 or 64
    int warpN = (wid & 3) * 32;      // 0,32,64,96
    int g  = lane >> 2;              // groupID 0..7
    int tg = lane & 3;               // thread-in-group 0..3
    // per-thread ldmatrix address components (x4 tile decomposition)
    int aRowIn = ((lane >> 3) & 1) * 8 + (lane & 7);
    int aColIn = ((lane >> 3) >> 1) * 4;

    float acc[4][4][4];
    #pragma unroll
    for (int i = 0; i < 4; i++)
        #pragma unroll
        for (int j = 0; j < 4; j++)
            #pragma unroll
            for (int r = 0; r < 4; r++) acc[i][j][r] = 0.f;

    int nTiles = Kk / 16;

    // prologue: load tile 0 and stage it
    aV0 = *(const float4*)(aPtr + 0 + aCol);
    aV1 = *(const float4*)(aPtr + 0 + aCol + 8);
    bV0 = *(const float4*)(bPtr + 0 + bN);
    bV1 = *(const float4*)(bPtr + 0 + bN + 64);
    {
        uint4 u0 = { f2tf32(aV0.x), f2tf32(aV0.y), f2tf32(aV0.z), f2tf32(aV0.w) };
        uint4 u1 = { f2tf32(aV1.x), f2tf32(aV1.y), f2tf32(aV1.z), f2tf32(aV1.w) };
        *(uint4*)&As[0][aRow][aCol]     = u0;
        *(uint4*)&As[0][aRow][aCol + 8] = u1;
        uint4 v0 = { f2tf32(bV0.x), f2tf32(bV0.y), f2tf32(bV0.z), f2tf32(bV0.w) };
        uint4 v1 = { f2tf32(bV1.x), f2tf32(bV1.y), f2tf32(bV1.z), f2tf32(bV1.w) };
        *(uint4*)&Bs[0][bK][bN]      = v0;
        *(uint4*)&Bs[0][bK][bN + 64] = v1;
    }
    __syncthreads();

    for (int t = 0; t < nTiles; t++) {
        int buf = t & 1;
        bool more = (t + 1 < nTiles);
        if (more) {
            int k0 = (t + 1) * 16;
            aV0 = *(const float4*)(aPtr + k0 + aCol);
            aV1 = *(const float4*)(aPtr + k0 + aCol + 8);
            const float* bp = bPtr + (size_t)k0 * Nn;
            bV0 = *(const float4*)(bp + bN);
            bV1 = *(const float4*)(bp + bN + 64);
        }

        #pragma unroll
        for (int s = 0; s < 2; s++) {
            unsigned af[4][4];
            #pragma unroll
            for (int i = 0; i < 4; i++)
                ldsm4(af[i][0], af[i][1], af[i][2], af[i][3],
                      &As[buf][warpM + i * 16 + aRowIn][s * 8 + aColIn]);
            unsigned bf[4][2];
            #pragma unroll
            for (int j = 0; j < 4; j++) {
                int col = warpN + j * 8 + g;
                bf[j][0] = Bs[buf][s * 8 + tg][col];
                bf[j][1] = Bs[buf][s * 8 + tg + 4][col];
            }
            #pragma unroll
            for (int i = 0; i < 4; i++)
                #pragma unroll
                for (int j = 0; j < 4; j++)
                    mma_tf32(acc[i][j], af[i], bf[j]);
        }

        if (more) {
            int nb = buf ^ 1;
            uint4 u0 = { f2tf32(aV0.x), f2tf32(aV0.y), f2tf32(aV0.z), f2tf32(aV0.w) };
            uint4 u1 = { f2tf32(aV1.x), f2tf32(aV1.y), f2tf32(aV1.z), f2tf32(aV1.w) };
            *(uint4*)&As[nb][aRow][aCol]     = u0;
            *(uint4*)&As[nb][aRow][aCol + 8] = u1;
            uint4 v0 = { f2tf32(bV0.x), f2tf32(bV0.y), f2tf32(bV0.z), f2tf32(bV0.w) };
            uint4 v1 = { f2tf32(bV1.x), f2tf32(bV1.y), f2tf32(bV1.z), f2tf32(bV1.w) };
            *(uint4*)&Bs[nb][bK][bN]      = v0;
            *(uint4*)&Bs[nb][bK][bN + 64] = v1;
        }
        __syncthreads();
    }

    // ---- epilogue ----
    #pragma unroll
    for (int i = 0; i < 4; i++) {
        int r0 = m0 + warpM + i * 16 + g;
        int r1 = r0 + 8;
        #pragma unroll
        for (int j = 0; j < 4; j++) {
            int col = n0 + warpN + j * 8 + tg * 2;
            float b0 = 0.f, b1 = 0.f;
            if (bias) { b0 = bias[col]; b1 = bias[col + 1]; }
            if (r0 < M) {
                float v0 = acc[i][j][0] + b0;
                float v1 = acc[i][j][1] + b1;
                if (ACT == 1) { v0 = gelu_f(v0); v1 = gelu_f(v1); }
                if (RESID) {
                    v0 += resid[(size_t)r0 * ldc + col];
                    v1 += resid[(size_t)r0 * ldc + col + 1];
                }
                *(float2*)&Cm[(size_t)r0 * ldc + col] = make_float2(v0, v1);
            }
            if (r1 < M) {
                float v2 = acc[i][j][2] + b0;
                float v3 = acc[i][j][3] + b1;
                if (ACT == 1) { v2 = gelu_f(v2); v3 = gelu_f(v3); }
                if (RESID) {
                    v2 += resid[(size_t)r1 * ldc + col];
                    v3 += resid[(size_t)r1 * ldc + col + 1];
                }
                *(float2*)&Cm[(size_t)r1 * ldc + col] = make_float2(v2, v3);
            }
        }
    }
}

// ---------------- attention ----------------
// raw scores S[bh][t][s] = (q.k) * C^-0.5 ; skip fully-masked tiles
__global__ __launch_bounds__(256) void attn_scores_kernel(const float* __restrict__ qkv,
                                                          float* __restrict__ S) {
    int bh = blockIdx.z;
    int t0 = blockIdx.y * 64, s0 = blockIdx.x * 64;
    if (s0 > t0) return;
    int b = bh / H_, h = bh - b * H_;

    __shared__ float Qs[64][65];
    __shared__ float Ks[64][65];
    int tid = threadIdx.x;
    const float* qb = qkv + (size_t)(b * T_ + t0) * C3_ + h * HS_;
    const float* kb = qkv + (size_t)(b * T_ + s0) * C3_ + C_ + h * HS_;
    #pragma unroll
    for (int l = 0; l < 16; l++) {
        int idx = tid + l * 256;
        int r = idx >> 6, d = idx & 63;
        Qs[d][r] = qb[(size_t)r * C3_ + d];
        Ks[d][r] = kb[(size_t)r * C3_ + d];
    }
    __syncthreads();

    int ty = tid >> 4, tx = tid & 15;
    int tb = ty * 4, sb = tx * 4;
    float acc[4][4] = {};
    #pragma unroll 16
    for (int d = 0; d < 64; d++) {
        float a0 = Qs[d][tb+0], a1 = Qs[d][tb+1], a2 = Qs[d][tb+2], a3 = Qs[d][tb+3];
        float b0 = Ks[d][sb+0], b1 = Ks[d][sb+1], b2 = Ks[d][sb+2], b3 = Ks[d][sb+3];
        acc[0][0]=fmaf(a0,b0,acc[0][0]); acc[0][1]=fmaf(a0,b1,acc[0][1]); acc[0][2]=fmaf(a0,b2,acc[0][2]); acc[0][3]=fmaf(a0,b3,acc[0][3]);
        acc[1][0]=fmaf(a1,b0,acc[1][0]); acc[1][1]=fmaf(a1,b1,acc[1][1]); acc[1][2]=fmaf(a1,b2,acc[1][2]); acc[1][3]=fmaf(a1,b3,acc[1][3]);
        acc[2][0]=fmaf(a2,b0,acc[2][0]); acc[2][1]=fmaf(a2,b1,acc[2][1]); acc[2][2]=fmaf(a2,b2,acc[2][2]); acc[2][3]=fmaf(a2,b3,acc[2][3]);
        acc[3][0]=fmaf(a3,b0,acc[3][0]); acc[3][1]=fmaf(a3,b1,acc[3][1]); acc[3][2]=fmaf(a3,b2,acc[3][2]); acc[3][3]=fmaf(a3,b3,acc[3][3]);
    }
    const float scale = 0.03608439182435161f;   // 768^-0.5
    float* op = S + ((size_t)bh * T_ + t0) * T_ + s0;
    #pragma unroll
    for (int i = 0; i < 4; i++)
        #pragma unroll
        for (int j = 0; j < 4; j++)
            op[(size_t)(tb + i) * T_ + sb + j] = acc[i][j] * scale;
}

// causal softmax in place: reads only s<=t, zeros s>t
__global__ __launch_bounds__(128) void softmax_causal_kernel(float* __restrict__ S) {
    int row = blockIdx.x;
    int t = row & (T_ - 1);
    float* p = S + (size_t)row * T_;
    int len = t + 1;
    int tid = threadIdx.x;
    __shared__ float sh[4];

    float mx = -1e30f;
    for (int s = tid; s < len; s += 128) mx = fmaxf(mx, p[s]);
    #pragma unroll
    for (int o = 16; o; o >>= 1) mx = fmaxf(mx, __shfl_down_sync(0xffffffffu, mx, o));
    if ((tid & 31) == 0) sh[tid >> 5] = mx;
    __syncthreads();
    mx = fmaxf(fmaxf(sh[0], sh[1]), fmaxf(sh[2], sh[3]));
    __syncthreads();

    float sum = 0.f;
    for (int s = tid; s < len; s += 128) { float e = __expf(p[s] - mx); p[s] = e; sum += e; }
    #pragma unroll
    for (int o = 16; o; o >>= 1) sum += __shfl_down_sync(0xffffffffu, sum, o);
    if ((tid & 31) == 0) sh[tid >> 5] = sum;
    __syncthreads();
    sum = sh[0] + sh[1] + sh[2] + sh[3];
    float inv = 1.f / sum;
    for (int s = tid; s < len; s += 128) p[s] *= inv;
    for (int s = len + tid; s < T_; s += 128) p[s] = 0.f;
}

// O = P @ V ; skips K-tiles that are all-zero (s0 > t)
__global__ __launch_bounds__(256) void attn_pv_kernel(const float* __restrict__ qkv,
                                                      const float* __restrict__ P,
                                                      float* __restrict__ O) {
    int bh = blockIdx.y;
    int b = bh / H_, h = bh - b * H_;
    int t0 = blockIdx.x * 64;

    __shared__ float Ps[64][65];
    __shared__ float Vs[64][65];
    int tid = threadIdx.x;
    int ty = tid >> 4, tx = tid & 15;
    int tb = ty * 4, db = tx * 4;
    float acc[4][4] = {};
    const float* prow = P + ((size_t)bh * T_ + t0) * T_;

    for (int s0 = 0; s0 <= t0; s0 += 64) {
        #pragma unroll
        for (int l = 0; l < 16; l++) {
            int idx = tid + l * 256;
            int a_ = idx >> 6, b_ = idx & 63;
            Ps[b_][a_] = prow[(size_t)a_ * T_ + s0 + b_];
            Vs[a_][b_] = qkv[(size_t)(b * T_ + s0 + a_) * C3_ + 2 * C_ + h * HS_ + b_];
        }
        __syncthreads();
        #pragma unroll 16
        for (int s = 0; s < 64; s++) {
            float a0 = Ps[s][tb+0], a1 = Ps[s][tb+1], a2 = Ps[s][tb+2], a3 = Ps[s][tb+3];
            float b0 = Vs[s][db+0], b1 = Vs[s][db+1], b2 = Vs[s][db+2], b3 = Vs[s][db+3];
            acc[0][0]=fmaf(a0,b0,acc[0][0]); acc[0][1]=fmaf(a0,b1,acc[0][1]); acc[0][2]=fmaf(a0,b2,acc[0][2]); acc[0][3]=fmaf(a0,b3,acc[0][3]);
            acc[1][0]=fmaf(a1,b0,acc[1][0]); acc[1][1]=fmaf(a1,b1,acc[1][1]); acc[1][2]=fmaf(a1,b2,acc[1][2]); acc[1][3]=fmaf(a1,b3,acc[1][3]);
            acc[2][0]=fmaf(a2,b0,acc[2][0]); acc[2][1]=fmaf(a2,b1,acc[2][1]); acc[2][2]=fmaf(a2,b2,acc[2][2]); acc[2][3]=fmaf(a2,b3,acc[2][3]);
            acc[3][0]=fmaf(a3,b0,acc[3][0]); acc[3][1]=fmaf(a3,b1,acc[3][1]); acc[3][2]=fmaf(a3,b2,acc[3][2]); acc[3][3]=fmaf(a3,b3,acc[3][3]);
        }
        __syncthreads();
    }
    #pragma unroll
    for (int i = 0; i < 4; i++)
        #pragma unroll
        for (int j = 0; j < 4; j++)
            O[(size_t)(b * T_ + t0 + tb + i) * C_ + h * HS_ + db + j] = acc[i][j];
}

// ---------------- router: noisy top-2 + assignment (one warp / token) ----------------
__global__ __launch_bounds__(256) void router_kernel(
    const float* __restrict__ h2,
    const float* __restrict__ wr, const float* __restrict__ br,
    const float* __restrict__ wn, const float* __restrict__ bn,
    const float* __restrict__ noise, const float* __restrict__ temp_p,
    int* __restrict__ cnt, int* __restrict__ tok, float* __restrict__ gw)
{
    int n = blockIdx.x * 8 + (threadIdx.x >> 5);
    if (n >= N_) return;
    int lane = threadIdx.x & 31;
    float ar[E_] = {}, an[E_] = {};
    const float* hp = h2 + (size_t)n * C_;
    for (int c = lane; c < C_; c += 32) {
        float hv = hp[c];
        const float* wrp = wr + c * E_;
        const float* wnp = wn + c * E_;
        #pragma unroll
        for (int e = 0; e < E_; e++) {
            ar[e] = fmaf(hv, wrp[e], ar[e]);
            an[e] = fmaf(hv, wnp[e], an[e]);
        }
    }
    #pragma unroll
    for (int e = 0; e < E_; e++) {
        #pragma unroll
        for (int o = 16; o; o >>= 1) {
            ar[e] += __shfl_down_sync(0xffffffffu, ar[e], o);
            an[e] += __shfl_down_sync(0xffffffffu, an[e], o);
        }
    }
    if (lane == 0) {
        float t = fminf(fmaxf(*temp_p, 0.5f), 2.0f);
        float noisy[E_];
        #pragma unroll
        for (int e = 0; e < E_; e++) {
            float logit = ar[e] + br[e];
            float z = an[e] + bn[e];
            float sp = fmaxf(z, 0.f) + log1pf(expf(-fabsf(z)));
            noisy[e] = logit + t * noise[(size_t)n * E_ + e] * sp;
        }
        int i1 = 0;
        #pragma unroll
        for (int e = 1; e < E_; e++) if (noisy[e] > noisy[i1]) i1 = e;
        int i2 = -1;
        #pragma unroll
        for (int e = 0; e < E_; e++)
            if (e != i1 && (i2 < 0 || noisy[e] > noisy[i2])) i2 = e;
        float m = fmaxf(noisy[i1], noisy[i2]);
        float e1 = __expf(noisy[i1] - m), e2 = __expf(noisy[i2] - m);
        float inv = 1.f / (e1 + e2);
        int p1 = atomicAdd(&cnt[i1], 1); tok[i1 * N_ + p1] = n; gw[i1 * N_ + p1] = e1 * inv;
        int p2 = atomicAdd(&cnt[i2], 1); tok[i2 * N_ + p2] = n; gw[i2 * N_ + p2] = e2 * inv;
    }
}

// ---------------- expert epilogue: out[n] += gate * LN(h2[n] + Y[m]) ----------------
__global__ __launch_bounds__(256) void expert_epi_kernel(
    const float* __restrict__ Y, const float* __restrict__ h2,
    const int* __restrict__ tok, const float* __restrict__ gw,
    const int* __restrict__ cnt,
    const float* __restrict__ lg, const float* __restrict__ lb,
    float* __restrict__ out)
{
    int m = blockIdx.x;
    if (m >= *cnt) return;
    int n = tok[m];
    float g = gw[m];
    const float* yp = Y + (size_t)m * C_;
    const float* hp = h2 + (size_t)n * C_;
    int t = threadIdx.x;
    float z0 = hp[t]       + yp[t];
    float z1 = hp[t + 256] + yp[t + 256];
    float z2 = hp[t + 512] + yp[t + 512];
    float mean = blockReduceSum256(z0 + z1 + z2) * (1.0f / C_);
    float d0 = z0 - mean, d1 = z1 - mean, d2 = z2 - mean;
    float var = blockReduceSum256(d0*d0 + d1*d1 + d2*d2) * (1.0f / C_);
    float rstd = rsqrtf(var + 1e-5f);
    float* op = out + (size_t)n * C_;
    op[t]       += g * (d0 * rstd * lg[t]       + lb[t]);
    op[t + 256] += g * (d1 * rstd * lg[t + 256] + lb[t + 256]);
    op[t + 512] += g * (d2 * rstd * lg[t + 512] + lb[t + 512]);
}

// ---------------- launch ----------------
extern "C" void kernel_launch(void* const* d_in, const int* in_sizes, int n_in,
                              void* d_out, int out_size) {
    const float* x         = (const float*)d_in[0];
    const float* rnoise    = (const float*)d_in[1];
    const float* wq        = (const float*)d_in[2];
    const float* wk        = (const float*)d_in[3];
    const float* wv        = (const float*)d_in[4];
    const float* w_proj    = (const float*)d_in[5];
    const float* b_proj    = (const float*)d_in[6];
    const float* ln1_g     = (const float*)d_in[7];
    const float* ln1_b     = (const float*)d_in[8];
    const float* ln2_g     = (const float*)d_in[9];
    const float* ln2_b     = (const float*)d_in[10];
    const float* w_route   = (const float*)d_in[11];
    const float* b_route   = (const float*)d_in[12];
    const float* w_noise   = (const float*)d_in[13];
    const float* b_noise   = (const float*)d_in[14];
    const float* temp      = (const float*)d_in[15];
    const float* deep_w1   = (const float*)d_in[16];
    const float* deep_b1   = (const float*)d_in[17];
    const float* deep_w2   = (const float*)d_in[18];
    const float* deep_b2   = (const float*)d_in[19];
    const float* deep_w3   = (const float*)d_in[20];
    const float* deep_b3   = (const float*)d_in[21];
    const float* deep_ln_g = (const float*)d_in[22];
    const float* deep_ln_b = (const float*)d_in[23];
    const float* simple_w1   = (const float*)d_in[24];
    const float* simple_b1   = (const float*)d_in[25];
    const float* simple_w2   = (const float*)d_in[26];
    const float* simple_b2   = (const float*)d_in[27];
    const float* simple_ln_g = (const float*)d_in[28];
    const float* simple_ln_b = (const float*)d_in[29];

    float* out = (float*)d_out;

    float *h1, *qkv, *S, *o, *h2, *mid1, *mid2, *Y, *Wqkv, *gw;
    int *cnt, *tok;
    cudaGetSymbolAddress((void**)&h1,   g_h1);
    cudaGetSymbolAddress((void**)&qkv,  g_qkv);
    cudaGetSymbolAddress((void**)&S,    g_S);
    cudaGetSymbolAddress((void**)&o,    g_o);
    cudaGetSymbolAddress((void**)&h2,   g_h2);
    cudaGetSymbolAddress((void**)&mid1, g_mid1);
    cudaGetSymbolAddress((void**)&mid2, g_mid2);
    cudaGetSymbolAddress((void**)&Y,    g_Y);
    cudaGetSymbolAddress((void**)&Wqkv, g_Wqkv);
    cudaGetSymbolAddress((void**)&cnt,  g_cnt);
    cudaGetSymbolAddress((void**)&tok,  g_tok);
    cudaGetSymbolAddress((void**)&gw,   g_gw);

    zero_cnt_kernel<<<1, 32>>>(cnt);
    pack_wqkv_kernel<<<(C_ * C3_ + 255) / 256, 256>>>(wq, wk, wv);

    // ln1 -> h1 ; qkv = h1 @ Wqkv
    ln_kernel<<<N_, 256>>>(x, ln1_g, ln1_b, h1);
    tgemm_k<false, 0, false><<<dim3(C3_ / 128, N_ / 128), 256>>>(
        h1, C_, Wqkv, nullptr, nullptr, qkv, C3_, N_, C3_, C_, nullptr, nullptr);

    // attention
    attn_scores_kernel<<<dim3(T_ / 64, T_ / 64, BH_), 256>>>(qkv, S);
    softmax_causal_kernel<<<BH_ * T_, 128>>>(S);
    attn_pv_kernel<<<dim3(T_ / 64, BH_), 256>>>(qkv, S, o);

    // out = x + o @ w_proj + b_proj   (out also serves as residual base x1)
    tgemm_k<false, 0, true><<<dim3(C_ / 128, N_ / 128), 256>>>(
        o, C_, w_proj, b_proj, x, out, C_, N_, C_, C_, nullptr, nullptr);

    // ln2 -> h2 ; router + token assignment
    ln_kernel<<<N_, 256>>>(out, ln2_g, ln2_b, h2);
    router_kernel<<<N_ / 8, 256>>>(h2, w_route, b_route, w_noise, b_noise,
                                   rnoise, temp, cnt, tok, gw);

    // deep experts (0..1): gelu(W1) -> gelu(W2) -> W3 -> LN accumulate
    for (int e = 0; e < 2; e++) {
        const int*   ce = cnt + e;
        const int*   te = tok + e * N_;
        const float* ge = gw + e * N_;
        tgemm_k<true, 1, false><<<dim3(F_ / 128, N_ / 128), 256>>>(
            h2, C_, deep_w1 + (size_t)e * C_ * F_, deep_b1 + (size_t)e * F_,
            nullptr, mid1, F_, N_, F_, C_, te, ce);
        tgemm_k<false, 1, false><<<dim3(F_ / 128, N_ / 128), 256>>>(
            mid1, F_, deep_w2 + (size_t)e * F_ * F_, deep_b2 + (size_t)e * F_,
            nullptr, mid2, F_, N_, F_, F_, nullptr, ce);
        tgemm_k<false, 0, false><<<dim3(C_ / 128, N_ / 128), 256>>>(
            mid2, F_, deep_w3 + (size_t)e * F_ * C_, deep_b3 + (size_t)e * C_,
            nullptr, Y, C_, N_, C_, F_, nullptr, ce);
        expert_epi_kernel<<<N_, 256>>>(Y, h2, te, ge, ce,
                                       deep_ln_g + (size_t)e * C_,
                                       deep_ln_b + (size_t)e * C_, out);
    }

    // simple experts (2..7): gelu(W1) -> W2 -> LN accumulate
    for (int e = 0; e < 6; e++) {
        int ee = 2 + e;
        const int*   ce = cnt + ee;
        const int*   te = tok + ee * N_;
        const float* ge = gw + ee * N_;
        tgemm_k<true, 1, false><<<dim3(F_ / 128, N_ / 128), 256>>>(
            h2, C_, simple_w1 + (size_t)e * C_ * F_, simple_b1 + (size_t)e * F_,
            nullptr, mid1, F_, N_, F_, C_, te, ce);
        tgemm_k<false, 0, false><<<dim3(C_ / 128, N_ / 128), 256>>>(
            mid1, F_, simple_w2 + (size_t)e * F_ * C_, simple_b2 + (size_t)e * C_,
            nullptr, Y, C_, N_, C_, F_, nullptr, ce);
        expert_epi_kernel<<<N_, 256>>>(Y, h2, te, ge, ce,
                                       simple_ln_g + (size_t)e * C_,
                                       simple_ln_b + (size_t)e * C_, out);
    }
}

// round 12
// speedup vs baseline: 1.1680x; 1.1680x over previous
#include <cuda_runtime.h>
#include <math.h>

// ---------------- problem constants ----------------
#define B_   8
#define T_   1024
#define C_   768
#define H_   12
#define HS_  64
#define E_   8
#define F_   3072
#define N_   (B_*T_)     // 8192 tokens
#define BH_  (B_*H_)     // 96
#define C3_  (3*C_)      // 2304

// rounded-weight scratch layout
#define PW_OFF   0
#define PW_SZ    (C_*C_)
#define DW1_OFF  (PW_OFF+PW_SZ)
#define DW1_SZ   (2*C_*F_)
#define DW2_OFF  (DW1_OFF+DW1_SZ)
#define DW2_SZ   (2*F_*F_)
#define DW3_OFF  (DW2_OFF+DW2_SZ)
#define DW3_SZ   (2*F_*C_)
#define SW1_OFF  (DW3_OFF+DW3_SZ)
#define SW1_SZ   (6*C_*F_)
#define SW2_OFF  (SW1_OFF+SW1_SZ)
#define SW2_SZ   (6*F_*C_)
#define WR_TOTAL (SW2_OFF+SW2_SZ)

// dynamic smem sizes
#define TG_SMEM  (4*(128*20 + 16*136)*4)     // 75776
#define SC_SMEM  ((128*68 + 64*136)*4)       // 69632
#define PV_SMEM  (4*(128*20 + 16*72)*4)      // 59392

// ---------------- scratch (device globals; no allocation) ----------------
__device__ float g_h1  [N_*C_];               // h1 (rounded), later h2r (rounded)
__device__ float g_qkv [N_*C3_];
__device__ float g_S   [(size_t)BH_*T_*T_];
__device__ float g_o   [N_*C_];
__device__ float g_h2  [N_*C_];               // exact h2
__device__ float g_mid1[N_*F_];
__device__ float g_mid2[N_*F_];
__device__ float g_Y   [N_*C_];
__device__ float g_Wqkv[C_*C3_];
__device__ float g_Wr  [WR_TOTAL];            // 229 MB rounded weights
__device__ int   g_cnt [E_];
__device__ int   g_tok [E_*N_];
__device__ float g_gw  [E_*N_];

// ---------------- helpers ----------------
__device__ __forceinline__ float gelu_f(float z) {
    return 0.5f * z * (1.0f + erff(z * 0.70710678118654752440f));
}

__device__ __forceinline__ float rna_tf32(float f) {
    unsigned r;
    asm("cvt.rna.tf32.f32 %0, %1;" : "=r"(r) : "f"(f));
    return __uint_as_float(r);
}

__device__ __forceinline__ void cpa16(void* smem_dst, const void* gsrc) {
    unsigned d = (unsigned)__cvta_generic_to_shared(smem_dst);
    asm volatile("cp.async.cg.shared.global [%0], [%1], 16;" :: "r"(d), "l"(gsrc));
}

__device__ __forceinline__ void ldsm4(unsigned &r0, unsigned &r1, unsigned &r2, unsigned &r3,
                                      const void* p) {
    unsigned addr = (unsigned)__cvta_generic_to_shared(p);
    asm volatile("ldmatrix.sync.aligned.m8n8.x4.shared.b16 {%0,%1,%2,%3}, [%4];"
        : "=r"(r0), "=r"(r1), "=r"(r2), "=r"(r3) : "r"(addr));
}

__device__ __forceinline__ void mma_tf32(float* c, const unsigned* a, const unsigned* b) {
    asm volatile("mma.sync.aligned.m16n8k8.row.col.f32.tf32.tf32.f32 "
        "{%0,%1,%2,%3}, {%4,%5,%6,%7}, {%8,%9}, {%0,%1,%2,%3};"
        : "+f"(c[0]), "+f"(c[1]), "+f"(c[2]), "+f"(c[3])
        : "r"(a[0]), "r"(a[1]), "r"(a[2]), "r"(a[3]), "r"(b[0]), "r"(b[1]));
}

__device__ __forceinline__ float blockReduceSum256(float v) {
    __shared__ float sh[8];
    int lane = threadIdx.x & 31, w = threadIdx.x >> 5;
    #pragma unroll
    for (int o = 16; o; o >>= 1) v += __shfl_down_sync(0xffffffffu, v, o);
    if (lane == 0) sh[w] = v;
    __syncthreads();
    float r;
    if (w == 0) {
        float t = (lane < 8) ? sh[lane] : 0.f;
        #pragma unroll
        for (int o = 4; o; o >>= 1) t += __shfl_down_sync(0xffffffffu, t, o);
        if (lane == 0) sh[0] = t;
    }
    __syncthreads();
    r = sh[0];
    __syncthreads();
    return r;
}

// ---------------- small setup kernels ----------------
__global__ void zero_cnt_kernel(int* cnt) {
    if (threadIdx.x < E_) cnt[threadIdx.x] = 0;
}

// round-copy weights to tf32
__global__ __launch_bounds__(256) void round_copy_kernel(const float* __restrict__ in,
                                                         float* __restrict__ out, int n4) {
    int i = blockIdx.x * 256 + threadIdx.x;
    if (i >= n4) return;
    float4 v = ((const float4*)in)[i];
    v.x = rna_tf32(v.x); v.y = rna_tf32(v.y); v.z = rna_tf32(v.z); v.w = rna_tf32(v.w);
    ((float4*)out)[i] = v;
}

// pack wq,wk,wv (H,C,HS) -> Wqkv[C][3C], rounded
__global__ void pack_wqkv_kernel(const float* __restrict__ wq,
                                 const float* __restrict__ wk,
                                 const float* __restrict__ wv) {
    int idx = blockIdx.x * 256 + threadIdx.x;
    if (idx >= C_ * C3_) return;
    int c   = idx / C3_;
    int col = idx - c * C3_;
    int which = col / C_;
    int rem   = col - which * C_;
    int h = rem / HS_;
    int d = rem - h * HS_;
    const float* w = (which == 0) ? wq : ((which == 1) ? wk : wv);
    g_Wqkv[idx] = rna_tf32(w[(h * C_ + c) * HS_ + d]);
}

// LayerNorm; ROUND_MAIN rounds main output; outR (optional) gets rounded copy
template<bool ROUND_MAIN>
__global__ __launch_bounds__(256) void ln_kernel(const float* __restrict__ in,
                                                 const float* __restrict__ g,
                                                 const float* __restrict__ b,
                                                 float* __restrict__ out,
                                                 float* __restrict__ outR) {
    int row = blockIdx.x;
    const float* p = in + (size_t)row * C_;
    int t = threadIdx.x;
    float x0 = p[t], x1 = p[t + 256], x2 = p[t + 512];
    float mean = blockReduceSum256(x0 + x1 + x2) * (1.0f / C_);
    float d0 = x0 - mean, d1 = x1 - mean, d2 = x2 - mean;
    float var = blockReduceSum256(d0*d0 + d1*d1 + d2*d2) * (1.0f / C_);
    float rstd = rsqrtf(var + 1e-5f);
    float v0 = d0 * rstd * g[t]       + b[t];
    float v1 = d1 * rstd * g[t + 256] + b[t + 256];
    float v2 = d2 * rstd * g[t + 512] + b[t + 512];
    float* o = out + (size_t)row * C_;
    if (ROUND_MAIN) {
        o[t] = rna_tf32(v0); o[t+256] = rna_tf32(v1); o[t+512] = rna_tf32(v2);
    } else {
        o[t] = v0; o[t+256] = v1; o[t+512] = v2;
    }
    if (outR) {
        float* r = outR + (size_t)row * C_;
        r[t] = rna_tf32(v0); r[t+256] = rna_tf32(v1); r[t+512] = rna_tf32(v2);
    }
}

// ---------------- tf32 GEMM, 4-stage cp.async pipeline ----------------
// C[m,n] = act(A[m,:] @ B[:,n] + bias[n]) (+resid) ; inputs pre-rounded to tf32.
// Block 128x128x16, 8 warps 2x4, warp tile 64x32. Nn%128==0, Kk%16==0.
template<bool GATHER, int ACT, bool RESID, bool ROUND>
__global__ __launch_bounds__(256) void tgemm_k(
    const float* __restrict__ A, int lda,
    const float* __restrict__ Bm,
    const float* __restrict__ bias,
    const float* __restrict__ resid,
    float* __restrict__ Cm, int ldc,
    int M, int Nn, int Kk,
    const int* __restrict__ rows,
    const int* __restrict__ cntPtr)
{
    if (cntPtr) M = *cntPtr;
    int m0 = blockIdx.y * 128;
    if (m0 >= M) return;
    int n0 = blockIdx.x * 128;

    extern __shared__ float sm[];
    float* sA = sm;                 // [4][128][20]
    float* sB = sm + 4*128*20;      // [4][16][136]
    __shared__ int rIdx[128];

    int tid = threadIdx.x;
    if (GATHER) {
        if (tid < 128) { int m = m0 + tid; rIdx[tid] = rows[(m < M) ? m : (M - 1)]; }
        __syncthreads();
    }

    int aRow = tid & 127;
    int aCol = (tid >> 7) * 4;       // {0,4}; second load at +8
    int aSrcRow;
    if (GATHER) aSrcRow = rIdx[aRow];
    else { int gm = m0 + aRow; aSrcRow = (gm < M) ? gm : (M - 1); }
    const float* aPtr = A + (size_t)aSrcRow * lda;
    int bK = tid >> 4;
    int bN = (tid & 15) * 4;
    const float* bPtr = Bm + (size_t)bK * Nn + n0;

    int nTiles = Kk / 16;

    // prologue: stages 0..2
    #pragma unroll
    for (int s = 0; s < 3; s++) {
        int k0 = s * 16;
        cpa16(&sA[((s*128) + aRow)*20 + aCol],     aPtr + k0 + aCol);
        cpa16(&sA[((s*128) + aRow)*20 + aCol + 8], aPtr + k0 + aCol + 8);
        const float* bp = bPtr + (size_t)k0 * Nn;
        cpa16(&sB[((s*16) + bK)*136 + bN],      bp + bN);
        cpa16(&sB[((s*16) + bK)*136 + bN + 64], bp + bN + 64);
        asm volatile("cp.async.commit_group;");
    }

    int wid = tid >> 5, lane = tid & 31;
    int warpM = (wid >> 2) * 64;
    int warpN = (wid & 3) * 32;
    int g  = lane >> 2;
    int tg = lane & 3;
    int aRowIn = ((lane >> 3) & 1) * 8 + (lane & 7);
    int aColIn = ((lane >> 3) >> 1) * 4;

    float acc[4][4][4];
    #pragma unroll
    for (int i = 0; i < 4; i++)
        #pragma unroll
        for (int j = 0; j < 4; j++)
            #pragma unroll
            for (int r = 0; r < 4; r++) acc[i][j][r] = 0.f;

    for (int t = 0; t < nTiles; t++) {
        asm volatile("cp.async.wait_group 2;");
        __syncthreads();
        int tn = t + 3;
        if (tn < nTiles) {
            int stg = tn & 3;
            int k0 = tn * 16;
            cpa16(&sA[((stg*128) + aRow)*20 + aCol],     aPtr + k0 + aCol);
            cpa16(&sA[((stg*128) + aRow)*20 + aCol + 8], aPtr + k0 + aCol + 8);
            const float* bp = bPtr + (size_t)k0 * Nn;
            cpa16(&sB[((stg*16) + bK)*136 + bN],      bp + bN);
            cpa16(&sB[((stg*16) + bK)*136 + bN + 64], bp + bN + 64);
        }
        asm volatile("cp.async.commit_group;");

        int buf = t & 3;
        const float* Ab = sA + buf*128*20;
        const float* Bb = sB + buf*16*136;
        #pragma unroll
        for (int s = 0; s < 2; s++) {
            unsigned af[4][4];
            #pragma unroll
            for (int i = 0; i < 4; i++)
                ldsm4(af[i][0], af[i][1], af[i][2], af[i][3],
                      &Ab[(warpM + i*16 + aRowIn)*20 + s*8 + aColIn]);
            unsigned bf[4][2];
            #pragma unroll
            for (int j = 0; j < 4; j++) {
                int col = warpN + j*8 + g;
                bf[j][0] = __float_as_uint(Bb[(s*8 + tg)*136 + col]);
                bf[j][1] = __float_as_uint(Bb[(s*8 + tg + 4)*136 + col]);
            }
            #pragma unroll
            for (int i = 0; i < 4; i++)
                #pragma unroll
                for (int j = 0; j < 4; j++)
                    mma_tf32(acc[i][j], af[i], bf[j]);
        }
    }

    // epilogue
    #pragma unroll
    for (int i = 0; i < 4; i++) {
        int r0 = m0 + warpM + i * 16 + g;
        int r1 = r0 + 8;
        #pragma unroll
        for (int j = 0; j < 4; j++) {
            int col = n0 + warpN + j * 8 + tg * 2;
            float b0 = 0.f, b1 = 0.f;
            if (bias) { b0 = bias[col]; b1 = bias[col + 1]; }
            if (r0 < M) {
                float v0 = acc[i][j][0] + b0;
                float v1 = acc[i][j][1] + b1;
                if (ACT == 1) { v0 = gelu_f(v0); v1 = gelu_f(v1); }
                if (RESID) {
                    v0 += resid[(size_t)r0 * ldc + col];
                    v1 += resid[(size_t)r0 * ldc + col + 1];
                }
                if (ROUND) { v0 = rna_tf32(v0); v1 = rna_tf32(v1); }
                *(float2*)&Cm[(size_t)r0 * ldc + col] = make_float2(v0, v1);
            }
            if (r1 < M) {
                float v2 = acc[i][j][2] + b0;
                float v3 = acc[i][j][3] + b1;
                if (ACT == 1) { v2 = gelu_f(v2); v3 = gelu_f(v3); }
                if (RESID) {
                    v2 += resid[(size_t)r1 * ldc + col];
                    v3 += resid[(size_t)r1 * ldc + col + 1];
                }
                if (ROUND) { v2 = rna_tf32(v2); v3 = rna_tf32(v3); }
                *(float2*)&Cm[(size_t)r1 * ldc + col] = make_float2(v2, v3);
            }
        }
    }
}

// ---------------- attention scores (tf32 mma) ----------------
// S tile [t0:t0+128][s0:s0+128] = Q·K^T * scale, lower-triangle tiles only.
__global__ __launch_bounds__(256) void attn_scores_tc(const float* __restrict__ qkv,
                                                      float* __restrict__ S) {
    int t0 = blockIdx.y * 128, s0 = blockIdx.x * 128;
    if (s0 > t0) return;
    int bh = blockIdx.z;
    int b = bh / H_, h = bh - b * H_;

    extern __shared__ float sm[];
    float* Qs = sm;              // [128][68]
    float* Ks = sm + 128*68;     // [64][136]  ([d][s])
    int tid = threadIdx.x;

    const float* qbase = qkv + (size_t)(b * T_ + t0) * C3_ + h * HS_;
    #pragma unroll
    for (int l = 0; l < 8; l++) {
        int idx = tid + l * 256;
        int r = idx >> 4, q = idx & 15;
        cpa16(&Qs[r*68 + q*4], qbase + (size_t)r * C3_ + q * 4);
    }
    asm volatile("cp.async.commit_group;");

    const float* kbase = qkv + (size_t)(b * T_ + s0) * C3_ + C_ + h * HS_;
    #pragma unroll
    for (int l = 0; l < 8; l++) {
        int idx = tid + l * 256;
        int s = idx & 127, q = idx >> 7;     // q 0..15
        float4 v = *(const float4*)(kbase + (size_t)s * C3_ + q * 4);
        Ks[(q*4+0)*136 + s] = v.x;
        Ks[(q*4+1)*136 + s] = v.y;
        Ks[(q*4+2)*136 + s] = v.z;
        Ks[(q*4+3)*136 + s] = v.w;
    }
    asm volatile("cp.async.wait_group 0;");
    __syncthreads();

    int wid = tid >> 5, lane = tid & 31;
    int warpM = (wid >> 2) * 64, warpN = (wid & 3) * 32;
    int g = lane >> 2, tg = lane & 3;
    int aRowIn = ((lane >> 3) & 1) * 8 + (lane & 7);
    int aColIn = ((lane >> 3) >> 1) * 4;

    float acc[4][4][4];
    #pragma unroll
    for (int i = 0; i < 4; i++)
        #pragma unroll
        for (int j = 0; j < 4; j++)
            #pragma unroll
            for (int r = 0; r < 4; r++) acc[i][j][r] = 0.f;

    #pragma unroll
    for (int ks = 0; ks < 8; ks++) {
        unsigned af[4][4];
        #pragma unroll
        for (int i = 0; i < 4; i++)
            ldsm4(af[i][0], af[i][1], af[i][2], af[i][3],
                  &Qs[(warpM + i*16 + aRowIn)*68 + ks*8 + aColIn]);
        unsigned bf[4][2];
        #pragma unroll
        for (int j = 0; j < 4; j++) {
            int col = warpN + j*8 + g;
            bf[j][0] = __float_as_uint(Ks[(ks*8 + tg)*136 + col]);
            bf[j][1] = __float_as_uint(Ks[(ks*8 + tg + 4)*136 + col]);
        }
        #pragma unroll
        for (int i = 0; i < 4; i++)
            #pragma unroll
            for (int j = 0; j < 4; j++)
                mma_tf32(acc[i][j], af[i], bf[j]);
    }

    const float scale = 0.03608439182435161f;   // 768^-0.5
    float* op = S + ((size_t)bh * T_ + t0) * T_ + s0;
    #pragma unroll
    for (int i = 0; i < 4; i++) {
        int r0 = warpM + i * 16 + g;
        int r1 = r0 + 8;
        #pragma unroll
        for (int j = 0; j < 4; j++) {
            int col = warpN + j * 8 + tg * 2;
            *(float2*)&op[(size_t)r0 * T_ + col] =
                make_float2(acc[i][j][0] * scale, acc[i][j][1] * scale);
            *(float2*)&op[(size_t)r1 * T_ + col] =
                make_float2(acc[i][j][2] * scale, acc[i][j][3] * scale);
        }
    }
}

// ---------------- causal softmax (in place, rounds P to tf32) ----------------
__global__ __launch_bounds__(128) void softmax_causal_kernel(float* __restrict__ S) {
    int row = blockIdx.x;
    int t = row & (T_ - 1);
    float* p = S + (size_t)row * T_;
    int len = t + 1;
    int tid = threadIdx.x;
    __shared__ float sh[4];

    float mx = -1e30f;
    for (int s = tid; s < len; s += 128) mx = fmaxf(mx, p[s]);
    #pragma unroll
    for (int o = 16; o; o >>= 1) mx = fmaxf(mx, __shfl_down_sync(0xffffffffu, mx, o));
    if ((tid & 31) == 0) sh[tid >> 5] = mx;
    __syncthreads();
    mx = fmaxf(fmaxf(sh[0], sh[1]), fmaxf(sh[2], sh[3]));
    __syncthreads();

    float sum = 0.f;
    for (int s = tid; s < len; s += 128) { float e = __expf(p[s] - mx); p[s] = e; sum += e; }
    #pragma unroll
    for (int o = 16; o; o >>= 1) sum += __shfl_down_sync(0xffffffffu, sum, o);
    if ((tid & 31) == 0) sh[tid >> 5] = sum;
    __syncthreads();
    sum = sh[0] + sh[1] + sh[2] + sh[3];
    float inv = 1.f / sum;
    for (int s = tid; s < len; s += 128) p[s] = rna_tf32(p[s] * inv);
    for (int s = len + tid; s < T_; s += 128) p[s] = 0.f;
}

// ---------------- PV (tf32 mma, cp.async pipelined) ----------------
// O[t][h*HS+d] = P[t][:] @ V[:][d], K limited to t0+128 by causality. Output rounded.
__global__ __launch_bounds__(256) void attn_pv_tc(const float* __restrict__ qkv,
                                                  const float* __restrict__ P,
                                                  float* __restrict__ O) {
    int t0 = blockIdx.x * 128;
    int bh = blockIdx.y;
    int b = bh / H_, h = bh - b * H_;

    extern __shared__ float sm[];
    float* sA = sm;                 // [4][128][20]
    float* sB = sm + 4*128*20;      // [4][16][72]

    int tid = threadIdx.x;
    const float* aPtr = P + ((size_t)bh * T_ + t0) * T_;
    const float* vbase = qkv + (size_t)(b * T_) * C3_ + 2 * C_ + h * HS_;

    int aRow = tid & 127;
    int aColQ = (tid >> 7) * 8;       // {0,8}; loads at aColQ and aColQ+4
    int bK = tid >> 4;
    int bN = (tid & 15) * 4;

    int nTiles = (t0 + 128) / 16;     // >= 8

    #pragma unroll
    for (int s = 0; s < 3; s++) {
        int k0 = s * 16;
        cpa16(&sA[((s*128) + aRow)*20 + aColQ],     aPtr + (size_t)aRow * T_ + k0 + aColQ);
        cpa16(&sA[((s*128) + aRow)*20 + aColQ + 4], aPtr + (size_t)aRow * T_ + k0 + aColQ + 4);
        cpa16(&sB[((s*16) + bK)*72 + bN], vbase + (size_t)(k0 + bK) * C3_ + bN);
        asm volatile("cp.async.commit_group;");
    }

    int wid = tid >> 5, lane = tid & 31;
    int warpM = (wid >> 1) * 32;      // 4 warps in M
    int warpN = (wid & 1) * 32;       // 2 warps in N
    int g = lane >> 2, tg = lane & 3;
    int aRowIn = ((lane >> 3) & 1) * 8 + (lane & 7);
    int aColIn = ((lane >> 3) >> 1) * 4;

    float acc[2][4][4];
    #pragma unroll
    for (int i = 0; i < 2; i++)
        #pragma unroll
        for (int j = 0; j < 4; j++)
            #pragma unroll
            for (int r = 0; r < 4; r++) acc[i][j][r] = 0.f;

    for (int t = 0; t < nTiles; t++) {
        asm volatile("cp.async.wait_group 2;");
        __syncthreads();
        int tn = t + 3;
        if (tn < nTiles) {
            int stg = tn & 3;
            int k0 = tn * 16;
            cpa16(&sA[((stg*128) + aRow)*20 + aColQ],     aPtr + (size_t)aRow * T_ + k0 + aColQ);
            cpa16(&sA[((stg*128) + aRow)*20 + aColQ + 4], aPtr + (size_t)aRow * T_ + k0 + aColQ + 4);
            cpa16(&sB[((stg*16) + bK)*72 + bN], vbase + (size_t)(k0 + bK) * C3_ + bN);
        }
        asm volatile("cp.async.commit_group;");

        int buf = t & 3;
        const float* Ab = sA + buf*128*20;
        const float* Bb = sB + buf*16*72;
        #pragma unroll
        for (int s = 0; s < 2; s++) {
            unsigned af[2][4];
            #pragma unroll
            for (int i = 0; i < 2; i++)
                ldsm4(af[i][0], af[i][1], af[i][2], af[i][3],
                      &Ab[(warpM + i*16 + aRowIn)*20 + s*8 + aColIn]);
            unsigned bf[4][2];
            #pragma unroll
            for (int j = 0; j < 4; j++) {
                int col = warpN + j*8 + g;
                bf[j][0] = __float_as_uint(Bb[(s*8 + tg)*72 + col]);
                bf[j][1] = __float_as_uint(Bb[(s*8 + tg + 4)*72 + col]);
            }
            #pragma unroll
            for (int i = 0; i < 2; i++)
                #pragma unroll
                for (int j = 0; j < 4; j++)
                    mma_tf32(acc[i][j], af[i], bf[j]);
        }
    }

    #pragma unroll
    for (int i = 0; i < 2; i++) {
        int r0 = warpM + i * 16 + g;
        int r1 = r0 + 8;
        #pragma unroll
        for (int j = 0; j < 4; j++) {
            int col = h * HS_ + warpN + j * 8 + tg * 2;
            *(float2*)&O[(size_t)(b * T_ + t0 + r0) * C_ + col] =
                make_float2(rna_tf32(acc[i][j][0]), rna_tf32(acc[i][j][1]));
            *(float2*)&O[(size_t)(b * T_ + t0 + r1) * C_ + col] =
                make_float2(rna_tf32(acc[i][j][2]), rna_tf32(acc[i][j][3]));
        }
    }
}

// ---------------- router (uses exact h2) ----------------
__global__ __launch_bounds__(256) void router_kernel(
    const float* __restrict__ h2,
    const float* __restrict__ wr, const float* __restrict__ br,
    const float* __restrict__ wn, const float* __restrict__ bn,
    const float* __restrict__ noise, const float* __restrict__ temp_p,
    int* __restrict__ cnt, int* __restrict__ tok, float* __restrict__ gw)
{
    int n = blockIdx.x * 8 + (threadIdx.x >> 5);
    if (n >= N_) return;
    int lane = threadIdx.x & 31;
    float ar[E_] = {}, an[E_] = {};
    const float* hp = h2 + (size_t)n * C_;
    for (int c = lane; c < C_; c += 32) {
        float hv = hp[c];
        const float* wrp = wr + c * E_;
        const float* wnp = wn + c * E_;
        #pragma unroll
        for (int e = 0; e < E_; e++) {
            ar[e] = fmaf(hv, wrp[e], ar[e]);
            an[e] = fmaf(hv, wnp[e], an[e]);
        }
    }
    #pragma unroll
    for (int e = 0; e < E_; e++) {
        #pragma unroll
        for (int o = 16; o; o >>= 1) {
            ar[e] += __shfl_down_sync(0xffffffffu, ar[e], o);
            an[e] += __shfl_down_sync(0xffffffffu, an[e], o);
        }
    }
    if (lane == 0) {
        float t = fminf(fmaxf(*temp_p, 0.5f), 2.0f);
        float noisy[E_];
        #pragma unroll
        for (int e = 0; e < E_; e++) {
            float logit = ar[e] + br[e];
            float z = an[e] + bn[e];
            float sp = fmaxf(z, 0.f) + log1pf(expf(-fabsf(z)));
            noisy[e] = logit + t * noise[(size_t)n * E_ + e] * sp;
        }
        int i1 = 0;
        #pragma unroll
        for (int e = 1; e < E_; e++) if (noisy[e] > noisy[i1]) i1 = e;
        int i2 = -1;
        #pragma unroll
        for (int e = 0; e < E_; e++)
            if (e != i1 && (i2 < 0 || noisy[e] > noisy[i2])) i2 = e;
        float m = fmaxf(noisy[i1], noisy[i2]);
        float e1 = __expf(noisy[i1] - m), e2 = __expf(noisy[i2] - m);
        float inv = 1.f / (e1 + e2);
        int p1 = atomicAdd(&cnt[i1], 1); tok[i1 * N_ + p1] = n; gw[i1 * N_ + p1] = e1 * inv;
        int p2 = atomicAdd(&cnt[i2], 1); tok[i2 * N_ + p2] = n; gw[i2 * N_ + p2] = e2 * inv;
    }
}

// ---------------- expert epilogue: out[n] += gate * LN(h2[n] + Y[m]) ----------------
__global__ __launch_bounds__(256) void expert_epi_kernel(
    const float* __restrict__ Y, const float* __restrict__ h2,
    const int* __restrict__ tok, const float* __restrict__ gw,
    const int* __restrict__ cnt,
    const float* __restrict__ lg, const float* __restrict__ lb,
    float* __restrict__ out)
{
    int m = blockIdx.x;
    if (m >= *cnt) return;
    int n = tok[m];
    float g = gw[m];
    const float* yp = Y + (size_t)m * C_;
    const float* hp = h2 + (size_t)n * C_;
    int t = threadIdx.x;
    float z0 = hp[t]       + yp[t];
    float z1 = hp[t + 256] + yp[t + 256];
    float z2 = hp[t + 512] + yp[t + 512];
    float mean = blockReduceSum256(z0 + z1 + z2) * (1.0f / C_);
    float d0 = z0 - mean, d1 = z1 - mean, d2 = z2 - mean;
    float var = blockReduceSum256(d0*d0 + d1*d1 + d2*d2) * (1.0f / C_);
    float rstd = rsqrtf(var + 1e-5f);
    float* op = out + (size_t)n * C_;
    op[t]       += g * (d0 * rstd * lg[t]       + lb[t]);
    op[t + 256] += g * (d1 * rstd * lg[t + 256] + lb[t + 256]);
    op[t + 512] += g * (d2 * rstd * lg[t + 512] + lb[t + 512]);
}

// ---------------- launch ----------------
extern "C" void kernel_launch(void* const* d_in, const int* in_sizes, int n_in,
                              void* d_out, int out_size) {
    const float* x         = (const float*)d_in[0];
    const float* rnoise    = (const float*)d_in[1];
    const float* wq        = (const float*)d_in[2];
    const float* wk        = (const float*)d_in[3];
    const float* wv        = (const float*)d_in[4];
    const float* w_proj    = (const float*)d_in[5];
    const float* b_proj    = (const float*)d_in[6];
    const float* ln1_g     = (const float*)d_in[7];
    const float* ln1_b     = (const float*)d_in[8];
    const float* ln2_g     = (const float*)d_in[9];
    const float* ln2_b     = (const float*)d_in[10];
    const float* w_route   = (const float*)d_in[11];
    const float* b_route   = (const float*)d_in[12];
    const float* w_noise   = (const float*)d_in[13];
    const float* b_noise   = (const float*)d_in[14];
    const float* temp      = (const float*)d_in[15];
    const float* deep_w1   = (const float*)d_in[16];
    const float* deep_b1   = (const float*)d_in[17];
    const float* deep_w2   = (const float*)d_in[18];
    const float* deep_b2   = (const float*)d_in[19];
    const float* deep_w3   = (const float*)d_in[20];
    const float* deep_b3   = (const float*)d_in[21];
    const float* deep_ln_g = (const float*)d_in[22];
    const float* deep_ln_b = (const float*)d_in[23];
    const float* simple_w1   = (const float*)d_in[24];
    const float* simple_b1   = (const float*)d_in[25];
    const float* simple_w2   = (const float*)d_in[26];
    const float* simple_b2   = (const float*)d_in[27];
    const float* simple_ln_g = (const float*)d_in[28];
    const float* simple_ln_b = (const float*)d_in[29];

    float* out = (float*)d_out;

    float *h1, *qkv, *S, *o, *h2, *mid1, *mid2, *Y, *Wqkv, *Wr, *gw;
    int *cnt, *tok;
    cudaGetSymbolAddress((void**)&h1,   g_h1);
    cudaGetSymbolAddress((void**)&qkv,  g_qkv);
    cudaGetSymbolAddress((void**)&S,    g_S);
    cudaGetSymbolAddress((void**)&o,    g_o);
    cudaGetSymbolAddress((void**)&h2,   g_h2);
    cudaGetSymbolAddress((void**)&mid1, g_mid1);
    cudaGetSymbolAddress((void**)&mid2, g_mid2);
    cudaGetSymbolAddress((void**)&Y,    g_Y);
    cudaGetSymbolAddress((void**)&Wqkv, g_Wqkv);
    cudaGetSymbolAddress((void**)&Wr,   g_Wr);
    cudaGetSymbolAddress((void**)&cnt,  g_cnt);
    cudaGetSymbolAddress((void**)&tok,  g_tok);
    cudaGetSymbolAddress((void**)&gw,   g_gw);

    // raise dynamic smem limits (idempotent)
    cudaFuncSetAttribute((const void*)tgemm_k<false,0,false,true>,  cudaFuncAttributeMaxDynamicSharedMemorySize, TG_SMEM);
    cudaFuncSetAttribute((const void*)tgemm_k<false,0,true,false>,  cudaFuncAttributeMaxDynamicSharedMemorySize, TG_SMEM);
    cudaFuncSetAttribute((const void*)tgemm_k<true,1,false,true>,   cudaFuncAttributeMaxDynamicSharedMemorySize, TG_SMEM);
    cudaFuncSetAttribute((const void*)tgemm_k<false,1,false,true>,  cudaFuncAttributeMaxDynamicSharedMemorySize, TG_SMEM);
    cudaFuncSetAttribute((const void*)tgemm_k<false,0,false,false>, cudaFuncAttributeMaxDynamicSharedMemorySize, TG_SMEM);
    cudaFuncSetAttribute((const void*)attn_scores_tc, cudaFuncAttributeMaxDynamicSharedMemorySize, SC_SMEM);
    cudaFuncSetAttribute((const void*)attn_pv_tc,     cudaFuncAttributeMaxDynamicSharedMemorySize, PV_SMEM);

    zero_cnt_kernel<<<1, 32>>>(cnt);
    pack_wqkv_kernel<<<(C_ * C3_ + 255) / 256, 256>>>(wq, wk, wv);

    // pre-round weights to tf32
    round_copy_kernel<<<PW_SZ/1024,  256>>>(w_proj,    Wr + PW_OFF,  PW_SZ/4);
    round_copy_kernel<<<DW1_SZ/1024, 256>>>(deep_w1,   Wr + DW1_OFF, DW1_SZ/4);
    round_copy_kernel<<<DW2_SZ/1024, 256>>>(deep_w2,   Wr + DW2_OFF, DW2_SZ/4);
    round_copy_kernel<<<DW3_SZ/1024, 256>>>(deep_w3,   Wr + DW3_OFF, DW3_SZ/4);
    round_copy_kernel<<<SW1_SZ/1024, 256>>>(simple_w1, Wr + SW1_OFF, SW1_SZ/4);
    round_copy_kernel<<<SW2_SZ/1024, 256>>>(simple_w2, Wr + SW2_OFF, SW2_SZ/4);

    // ln1 -> h1 (rounded) ; qkv = h1 @ Wqkv (rounded out)
    ln_kernel<true><<<N_, 256>>>(x, ln1_g, ln1_b, h1, nullptr);
    tgemm_k<false, 0, false, true><<<dim3(C3_ / 128, N_ / 128), 256, TG_SMEM>>>(
        h1, C_, Wqkv, nullptr, nullptr, qkv, C3_, N_, C3_, C_, nullptr, nullptr);

    // attention (tensor core)
    attn_scores_tc<<<dim3(T_ / 128, T_ / 128, BH_), 256, SC_SMEM>>>(qkv, S);
    softmax_causal_kernel<<<BH_ * T_, 128>>>(S);
    attn_pv_tc<<<dim3(T_ / 128, BH_), 256, PV_SMEM>>>(qkv, S, o);

    // out = x + o @ w_proj + b_proj
    tgemm_k<false, 0, true, false><<<dim3(C_ / 128, N_ / 128), 256, TG_SMEM>>>(
        o, C_, Wr + PW_OFF, b_proj, x, out, C_, N_, C_, C_, nullptr, nullptr);

    // ln2 -> h2 (exact) + h2r (rounded, reuses h1 buffer) ; router
    ln_kernel<false><<<N_, 256>>>(out, ln2_g, ln2_b, h2, h1);
    router_kernel<<<N_ / 8, 256>>>(h2, w_route, b_route, w_noise, b_noise,
                                   rnoise, temp, cnt, tok, gw);

    // deep experts (0..1)
    for (int e = 0; e < 2; e++) {
        const int*   ce = cnt + e;
        const int*   te = tok + e * N_;
        const float* ge = gw + e * N_;
        tgemm_k<true, 1, false, true><<<dim3(F_ / 128, N_ / 128), 256, TG_SMEM>>>(
            h1, C_, Wr + DW1_OFF + (size_t)e * C_ * F_, deep_b1 + (size_t)e * F_,
            nullptr, mid1, F_, N_, F_, C_, te, ce);
        tgemm_k<false, 1, false, true><<<dim3(F_ / 128, N_ / 128), 256, TG_SMEM>>>(
            mid1, F_, Wr + DW2_OFF + (size_t)e * F_ * F_, deep_b2 + (size_t)e * F_,
            nullptr, mid2, F_, N_, F_, F_, nullptr, ce);
        tgemm_k<false, 0, false, false><<<dim3(C_ / 128, N_ / 128), 256, TG_SMEM>>>(
            mid2, F_, Wr + DW3_OFF + (size_t)e * F_ * C_, deep_b3 + (size_t)e * C_,
            nullptr, Y, C_, N_, C_, F_, nullptr, ce);
        expert_epi_kernel<<<N_, 256>>>(Y, h2, te, ge, ce,
                                       deep_ln_g + (size_t)e * C_,
                                       deep_ln_b + (size_t)e * C_, out);
    }

    // simple experts (2..7)
    for (int e = 0; e < 6; e++) {
        int ee = 2 + e;
        const int*   ce = cnt + ee;
        const int*   te = tok + ee * N_;
        const float* ge = gw + ee * N_;
        tgemm_k<true, 1, false, true><<<dim3(F_ / 128, N_ / 128), 256, TG_SMEM>>>(
            h1, C_, Wr + SW1_OFF + (size_t)e * C_ * F_, simple_b1 + (size_t)e * F_,
            nullptr, mid1, F_, N_, F_, C_, te, ce);
        tgemm_k<false, 0, false, false><<<dim3(C_ / 128, N_ / 128), 256, TG_SMEM>>>(
            mid1, F_, Wr + SW2_OFF + (size_t)e * F_ * C_, simple_b2 + (size_t)e * C_,
            nullptr, Y, C_, N_, C_, F_, nullptr, ce);
        expert_epi_kernel<<<N_, 256>>>(Y, h2, te, ge, ce,
                                       simple_ln_g + (size_t)e * C_,
                                       simple_ln_b + (size_t)e * C_, out);
    }
}

// round 13
// speedup vs baseline: 1.1696x; 1.0014x over previous
#include <cuda_runtime.h>
#include <math.h>

// ---------------- problem constants ----------------
#define B_   8
#define T_   1024
#define C_   768
#define H_   12
#define HS_  64
#define E_   8
#define F_   3072
#define N_   (B_*T_)     // 8192 tokens
#define BH_  (B_*H_)     // 96
#define C3_  (3*C_)      // 2304

// rounded-weight scratch layout
#define PW_OFF   0
#define PW_SZ    (C_*C_)
#define DW1_OFF  (PW_OFF+PW_SZ)
#define DW1_SZ   (2*C_*F_)
#define DW2_OFF  (DW1_OFF+DW1_SZ)
#define DW2_SZ   (2*F_*F_)
#define DW3_OFF  (DW2_OFF+DW2_SZ)
#define DW3_SZ   (2*F_*C_)
#define SW1_OFF  (DW3_OFF+DW3_SZ)
#define SW1_SZ   (6*C_*F_)
#define SW2_OFF  (SW1_OFF+SW1_SZ)
#define SW2_SZ   (6*F_*C_)
#define WR_TOTAL (SW2_OFF+SW2_SZ)

// dynamic smem sizes
#define TG_SMEM  (4*(128*20 + 16*136)*4)     // 75776
#define SC_SMEM  ((128*68 + 64*136)*4)       // 69632
#define PV_SMEM  (4*(128*20 + 16*72)*4)      // 59392

// ---------------- scratch (device globals; no allocation) ----------------
__device__ float g_h1  [N_*C_];               // h1 (rounded), later h2r (rounded)
__device__ float g_qkv [N_*C3_];
__device__ float g_S   [(size_t)BH_*T_*T_];
__device__ float g_o   [N_*C_];
__device__ float g_h2  [N_*C_];               // exact h2
__device__ float g_mid1[N_*F_];
__device__ float g_mid2[N_*F_];
__device__ float g_Y   [N_*C_];
__device__ float g_Wqkv[C_*C3_];
__device__ float g_Wr  [WR_TOTAL];            // 229 MB rounded weights
__device__ int   g_cnt [E_];
__device__ int   g_tok [E_*N_];
__device__ float g_gw  [E_*N_];

// ---------------- helpers ----------------
__device__ __forceinline__ float gelu_f(float z) {
    return 0.5f * z * (1.0f + erff(z * 0.70710678118654752440f));
}

__device__ __forceinline__ float rna_tf32(float f) {
    unsigned r;
    asm("cvt.rna.tf32.f32 %0, %1;" : "=r"(r) : "f"(f));
    return __uint_as_float(r);
}

__device__ __forceinline__ void cpa16(void* smem_dst, const void* gsrc) {
    unsigned d = (unsigned)__cvta_generic_to_shared(smem_dst);
    asm volatile("cp.async.cg.shared.global [%0], [%1], 16;" :: "r"(d), "l"(gsrc));
}

__device__ __forceinline__ void ldsm4(unsigned &r0, unsigned &r1, unsigned &r2, unsigned &r3,
                                      const void* p) {
    unsigned addr = (unsigned)__cvta_generic_to_shared(p);
    asm volatile("ldmatrix.sync.aligned.m8n8.x4.shared.b16 {%0,%1,%2,%3}, [%4];"
        : "=r"(r0), "=r"(r1), "=r"(r2), "=r"(r3) : "r"(addr));
}

__device__ __forceinline__ void mma_tf32(float* c, const unsigned* a, const unsigned* b) {
    asm volatile("mma.sync.aligned.m16n8k8.row.col.f32.tf32.tf32.f32 "
        "{%0,%1,%2,%3}, {%4,%5,%6,%7}, {%8,%9}, {%0,%1,%2,%3};"
        : "+f"(c[0]), "+f"(c[1]), "+f"(c[2]), "+f"(c[3])
        : "r"(a[0]), "r"(a[1]), "r"(a[2]), "r"(a[3]), "r"(b[0]), "r"(b[1]));
}

__device__ __forceinline__ float blockReduceSum256(float v) {
    __shared__ float sh[8];
    int lane = threadIdx.x & 31, w = threadIdx.x >> 5;
    #pragma unroll
    for (int o = 16; o; o >>= 1) v += __shfl_down_sync(0xffffffffu, v, o);
    if (lane == 0) sh[w] = v;
    __syncthreads();
    float r;
    if (w == 0) {
        float t = (lane < 8) ? sh[lane] : 0.f;
        #pragma unroll
        for (int o = 4; o; o >>= 1) t += __shfl_down_sync(0xffffffffu, t, o);
        if (lane == 0) sh[0] = t;
    }
    __syncthreads();
    r = sh[0];
    __syncthreads();
    return r;
}

// ---------------- small setup kernels ----------------
__global__ void zero_cnt_kernel(int* cnt) {
    if (threadIdx.x < E_) cnt[threadIdx.x] = 0;
}

// round-copy weights to tf32
__global__ __launch_bounds__(256) void round_copy_kernel(const float* __restrict__ in,
                                                         float* __restrict__ out, int n4) {
    int i = blockIdx.x * 256 + threadIdx.x;
    if (i >= n4) return;
    float4 v = ((const float4*)in)[i];
    v.x = rna_tf32(v.x); v.y = rna_tf32(v.y); v.z = rna_tf32(v.z); v.w = rna_tf32(v.w);
    ((float4*)out)[i] = v;
}

// pack wq,wk,wv (H,C,HS) -> Wqkv[C][3C], rounded
__global__ void pack_wqkv_kernel(const float* __restrict__ wq,
                                 const float* __restrict__ wk,
                                 const float* __restrict__ wv) {
    int idx = blockIdx.x * 256 + threadIdx.x;
    if (idx >= C_ * C3_) return;
    int c   = idx / C3_;
    int col = idx - c * C3_;
    int which = col / C_;
    int rem   = col - which * C_;
    int h = rem / HS_;
    int d = rem - h * HS_;
    const float* w = (which == 0) ? wq : ((which == 1) ? wk : wv);
    g_Wqkv[idx] = rna_tf32(w[(h * C_ + c) * HS_ + d]);
}

// LayerNorm; ROUND_MAIN rounds main output; outR (optional) gets rounded copy
template<bool ROUND_MAIN>
__global__ __launch_bounds__(256) void ln_kernel(const float* __restrict__ in,
                                                 const float* __restrict__ g,
                                                 const float* __restrict__ b,
                                                 float* __restrict__ out,
                                                 float* __restrict__ outR) {
    int row = blockIdx.x;
    const float* p = in + (size_t)row * C_;
    int t = threadIdx.x;
    float x0 = p[t], x1 = p[t + 256], x2 = p[t + 512];
    float mean = blockReduceSum256(x0 + x1 + x2) * (1.0f / C_);
    float d0 = x0 - mean, d1 = x1 - mean, d2 = x2 - mean;
    float var = blockReduceSum256(d0*d0 + d1*d1 + d2*d2) * (1.0f / C_);
    float rstd = rsqrtf(var + 1e-5f);
    float v0 = d0 * rstd * g[t]       + b[t];
    float v1 = d1 * rstd * g[t + 256] + b[t + 256];
    float v2 = d2 * rstd * g[t + 512] + b[t + 512];
    float* o = out + (size_t)row * C_;
    if (ROUND_MAIN) {
        o[t] = rna_tf32(v0); o[t+256] = rna_tf32(v1); o[t+512] = rna_tf32(v2);
    } else {
        o[t] = v0; o[t+256] = v1; o[t+512] = v2;
    }
    if (outR) {
        float* r = outR + (size_t)row * C_;
        r[t] = rna_tf32(v0); r[t+256] = rna_tf32(v1); r[t+512] = rna_tf32(v2);
    }
}

// ---------------- tf32 GEMM, 4-stage cp.async pipeline ----------------
// C[m,n] = act(A[m,:] @ B[:,n] + bias[n]) (+resid) ; inputs pre-rounded to tf32.
// Block 128x128x16, 8 warps 2x4, warp tile 64x32. Nn%128==0, Kk%16==0.
template<bool GATHER, int ACT, bool RESID, bool ROUND>
__global__ __launch_bounds__(256) void tgemm_k(
    const float* __restrict__ A, int lda,
    const float* __restrict__ Bm,
    const float* __restrict__ bias,
    const float* __restrict__ resid,
    float* __restrict__ Cm, int ldc,
    int M, int Nn, int Kk,
    const int* __restrict__ rows,
    const int* __restrict__ cntPtr)
{
    if (cntPtr) M = *cntPtr;
    int m0 = blockIdx.y * 128;
    if (m0 >= M) return;
    int n0 = blockIdx.x * 128;

    extern __shared__ float sm[];
    float* sA = sm;                 // [4][128][20]
    float* sB = sm + 4*128*20;      // [4][16][136]
    __shared__ int rIdx[128];

    int tid = threadIdx.x;
    if (GATHER) {
        if (tid < 128) { int m = m0 + tid; rIdx[tid] = rows[(m < M) ? m : (M - 1)]; }
        __syncthreads();
    }

    int aRow = tid & 127;
    int aCol = (tid >> 7) * 4;       // {0,4}; second load at +8
    int aSrcRow;
    if (GATHER) aSrcRow = rIdx[aRow];
    else { int gm = m0 + aRow; aSrcRow = (gm < M) ? gm : (M - 1); }
    const float* aPtr = A + (size_t)aSrcRow * lda;
    int bK = tid >> 4;
    int bN = (tid & 15) * 4;
    const float* bPtr = Bm + (size_t)bK * Nn + n0;

    int nTiles = Kk / 16;

    // prologue: stages 0..2
    #pragma unroll
    for (int s = 0; s < 3; s++) {
        int k0 = s * 16;
        cpa16(&sA[((s*128) + aRow)*20 + aCol],     aPtr + k0 + aCol);
        cpa16(&sA[((s*128) + aRow)*20 + aCol + 8], aPtr + k0 + aCol + 8);
        const float* bp = bPtr + (size_t)k0 * Nn;
        cpa16(&sB[((s*16) + bK)*136 + bN],      bp + bN);
        cpa16(&sB[((s*16) + bK)*136 + bN + 64], bp + bN + 64);
        asm volatile("cp.async.commit_group;");
    }

    int wid = tid >> 5, lane = tid & 31;
    int warpM = (wid >> 2) * 64;
    int warpN = (wid & 3) * 32;
    int g  = lane >> 2;
    int tg = lane & 3;
    int aRowIn = ((lane >> 3) & 1) * 8 + (lane & 7);
    int aColIn = ((lane >> 3) >> 1) * 4;

    float acc[4][4][4];
    #pragma unroll
    for (int i = 0; i < 4; i++)
        #pragma unroll
        for (int j = 0; j < 4; j++)
            #pragma unroll
            for (int r = 0; r < 4; r++) acc[i][j][r] = 0.f;

    for (int t = 0; t < nTiles; t++) {
        asm volatile("cp.async.wait_group 2;");
        __syncthreads();
        int tn = t + 3;
        if (tn < nTiles) {
            int stg = tn & 3;
            int k0 = tn * 16;
            cpa16(&sA[((stg*128) + aRow)*20 + aCol],     aPtr + k0 + aCol);
            cpa16(&sA[((stg*128) + aRow)*20 + aCol + 8], aPtr + k0 + aCol + 8);
            const float* bp = bPtr + (size_t)k0 * Nn;
            cpa16(&sB[((stg*16) + bK)*136 + bN],      bp + bN);
            cpa16(&sB[((stg*16) + bK)*136 + bN + 64], bp + bN + 64);
        }
        asm volatile("cp.async.commit_group;");

        int buf = t & 3;
        const float* Ab = sA + buf*128*20;
        const float* Bb = sB + buf*16*136;
        #pragma unroll
        for (int s = 0; s < 2; s++) {
            unsigned af[4][4];
            #pragma unroll
            for (int i = 0; i < 4; i++)
                ldsm4(af[i][0], af[i][1], af[i][2], af[i][3],
                      &Ab[(warpM + i*16 + aRowIn)*20 + s*8 + aColIn]);
            unsigned bf[4][2];
            #pragma unroll
            for (int j = 0; j < 4; j++) {
                int col = warpN + j*8 + g;
                bf[j][0] = __float_as_uint(Bb[(s*8 + tg)*136 + col]);
                bf[j][1] = __float_as_uint(Bb[(s*8 + tg + 4)*136 + col]);
            }
            #pragma unroll
            for (int i = 0; i < 4; i++)
                #pragma unroll
                for (int j = 0; j < 4; j++)
                    mma_tf32(acc[i][j], af[i], bf[j]);
        }
    }

    // epilogue
    #pragma unroll
    for (int i = 0; i < 4; i++) {
        int r0 = m0 + warpM + i * 16 + g;
        int r1 = r0 + 8;
        #pragma unroll
        for (int j = 0; j < 4; j++) {
            int col = n0 + warpN + j * 8 + tg * 2;
            float b0 = 0.f, b1 = 0.f;
            if (bias) { b0 = bias[col]; b1 = bias[col + 1]; }
            if (r0 < M) {
                float v0 = acc[i][j][0] + b0;
                float v1 = acc[i][j][1] + b1;
                if (ACT == 1) { v0 = gelu_f(v0); v1 = gelu_f(v1); }
                if (RESID) {
                    v0 += resid[(size_t)r0 * ldc + col];
                    v1 += resid[(size_t)r0 * ldc + col + 1];
                }
                if (ROUND) { v0 = rna_tf32(v0); v1 = rna_tf32(v1); }
                *(float2*)&Cm[(size_t)r0 * ldc + col] = make_float2(v0, v1);
            }
            if (r1 < M) {
                float v2 = acc[i][j][2] + b0;
                float v3 = acc[i][j][3] + b1;
                if (ACT == 1) { v2 = gelu_f(v2); v3 = gelu_f(v3); }
                if (RESID) {
                    v2 += resid[(size_t)r1 * ldc + col];
                    v3 += resid[(size_t)r1 * ldc + col + 1];
                }
                if (ROUND) { v2 = rna_tf32(v2); v3 = rna_tf32(v3); }
                *(float2*)&Cm[(size_t)r1 * ldc + col] = make_float2(v2, v3);
            }
        }
    }
}

// ---------------- attention scores (tf32 mma) ----------------
// S tile [t0:t0+128][s0:s0+128] = Q·K^T * scale, lower-triangle tiles only.
__global__ __launch_bounds__(256) void attn_scores_tc(const float* __restrict__ qkv,
                                                      float* __restrict__ S) {
    int t0 = blockIdx.y * 128, s0 = blockIdx.x * 128;
    if (s0 > t0) return;
    int bh = blockIdx.z;
    int b = bh / H_, h = bh - b * H_;

    extern __shared__ float sm[];
    float* Qs = sm;              // [128][68]
    float* Ks = sm + 128*68;     // [64][136]  ([d][s])
    int tid = threadIdx.x;

    const float* qbase = qkv + (size_t)(b * T_ + t0) * C3_ + h * HS_;
    #pragma unroll
    for (int l = 0; l < 8; l++) {
        int idx = tid + l * 256;
        int r = idx >> 4, q = idx & 15;
        cpa16(&Qs[r*68 + q*4], qbase + (size_t)r * C3_ + q * 4);
    }
    asm volatile("cp.async.commit_group;");

    const float* kbase = qkv + (size_t)(b * T_ + s0) * C3_ + C_ + h * HS_;
    #pragma unroll
    for (int l = 0; l < 8; l++) {
        int idx = tid + l * 256;
        int s = idx & 127, q = idx >> 7;     // q 0..15
        float4 v = *(const float4*)(kbase + (size_t)s * C3_ + q * 4);
        Ks[(q*4+0)*136 + s] = v.x;
        Ks[(q*4+1)*136 + s] = v.y;
        Ks[(q*4+2)*136 + s] = v.z;
        Ks[(q*4+3)*136 + s] = v.w;
    }
    asm volatile("cp.async.wait_group 0;");
    __syncthreads();

    int wid = tid >> 5, lane = tid & 31;
    int warpM = (wid >> 2) * 64, warpN = (wid & 3) * 32;
    int g = lane >> 2, tg = lane & 3;
    int aRowIn = ((lane >> 3) & 1) * 8 + (lane & 7);
    int aColIn = ((lane >> 3) >> 1) * 4;

    float acc[4][4][4];
    #pragma unroll
    for (int i = 0; i < 4; i++)
        #pragma unroll
        for (int j = 0; j < 4; j++)
            #pragma unroll
            for (int r = 0; r < 4; r++) acc[i][j][r] = 0.f;

    #pragma unroll
    for (int ks = 0; ks < 8; ks++) {
        unsigned af[4][4];
        #pragma unroll
        for (int i = 0; i < 4; i++)
            ldsm4(af[i][0], af[i][1], af[i][2], af[i][3],
                  &Qs[(warpM + i*16 + aRowIn)*68 + ks*8 + aColIn]);
        unsigned bf[4][2];
        #pragma unroll
        for (int j = 0; j < 4; j++) {
            int col = warpN + j*8 + g;
            bf[j][0] = __float_as_uint(Ks[(ks*8 + tg)*136 + col]);
            bf[j][1] = __float_as_uint(Ks[(ks*8 + tg + 4)*136 + col]);
        }
        #pragma unroll
        for (int i = 0; i < 4; i++)
            #pragma unroll
            for (int j = 0; j < 4; j++)
                mma_tf32(acc[i][j], af[i], bf[j]);
    }

    const float scale = 0.03608439182435161f;   // 768^-0.5
    float* op = S + ((size_t)bh * T_ + t0) * T_ + s0;
    #pragma unroll
    for (int i = 0; i < 4; i++) {
        int r0 = warpM + i * 16 + g;
        int r1 = r0 + 8;
        #pragma unroll
        for (int j = 0; j < 4; j++) {
            int col = warpN + j * 8 + tg * 2;
            *(float2*)&op[(size_t)r0 * T_ + col] =
                make_float2(acc[i][j][0] * scale, acc[i][j][1] * scale);
            *(float2*)&op[(size_t)r1 * T_ + col] =
                make_float2(acc[i][j][2] * scale, acc[i][j][3] * scale);
        }
    }
}

// ---------------- causal softmax (in place, rounds P to tf32) ----------------
__global__ __launch_bounds__(128) void softmax_causal_kernel(float* __restrict__ S) {
    int row = blockIdx.x;
    int t = row & (T_ - 1);
    float* p = S + (size_t)row * T_;
    int len = t + 1;
    int tid = threadIdx.x;
    __shared__ float sh[4];

    float mx = -1e30f;
    for (int s = tid; s < len; s += 128) mx = fmaxf(mx, p[s]);
    #pragma unroll
    for (int o = 16; o; o >>= 1) mx = fmaxf(mx, __shfl_down_sync(0xffffffffu, mx, o));
    if ((tid & 31) == 0) sh[tid >> 5] = mx;
    __syncthreads();
    mx = fmaxf(fmaxf(sh[0], sh[1]), fmaxf(sh[2], sh[3]));
    __syncthreads();

    float sum = 0.f;
    for (int s = tid; s < len; s += 128) { float e = __expf(p[s] - mx); p[s] = e; sum += e; }
    #pragma unroll
    for (int o = 16; o; o >>= 1) sum += __shfl_down_sync(0xffffffffu, sum, o);
    if ((tid & 31) == 0) sh[tid >> 5] = sum;
    __syncthreads();
    sum = sh[0] + sh[1] + sh[2] + sh[3];
    float inv = 1.f / sum;
    for (int s = tid; s < len; s += 128) p[s] = rna_tf32(p[s] * inv);
    for (int s = len + tid; s < T_; s += 128) p[s] = 0.f;
}

// ---------------- PV (tf32 mma, cp.async pipelined) ----------------
// O[t][h*HS+d] = P[t][:] @ V[:][d], K limited to t0+128 by causality. Output rounded.
__global__ __launch_bounds__(256) void attn_pv_tc(const float* __restrict__ qkv,
                                                  const float* __restrict__ P,
                                                  float* __restrict__ O) {
    int t0 = blockIdx.x * 128;
    int bh = blockIdx.y;
    int b = bh / H_, h = bh - b * H_;

    extern __shared__ float sm[];
    float* sA = sm;                 // [4][128][20]
    float* sB = sm + 4*128*20;      // [4][16][72]

    int tid = threadIdx.x;
    const float* aPtr = P + ((size_t)bh * T_ + t0) * T_;
    const float* vbase = qkv + (size_t)(b * T_) * C3_ + 2 * C_ + h * HS_;

    int aRow = tid & 127;
    int aColQ = (tid >> 7) * 8;       // {0,8}; loads at aColQ and aColQ+4
    int bK = tid >> 4;
    int bN = (tid & 15) * 4;

    int nTiles = (t0 + 128) / 16;     // >= 8

    #pragma unroll
    for (int s = 0; s < 3; s++) {
        int k0 = s * 16;
        cpa16(&sA[((s*128) + aRow)*20 + aColQ],     aPtr + (size_t)aRow * T_ + k0 + aColQ);
        cpa16(&sA[((s*128) + aRow)*20 + aColQ + 4], aPtr + (size_t)aRow * T_ + k0 + aColQ + 4);
        cpa16(&sB[((s*16) + bK)*72 + bN], vbase + (size_t)(k0 + bK) * C3_ + bN);
        asm volatile("cp.async.commit_group;");
    }

    int wid = tid >> 5, lane = tid & 31;
    int warpM = (wid >> 1) * 32;      // 4 warps in M
    int warpN = (wid & 1) * 32;       // 2 warps in N
    int g = lane >> 2, tg = lane & 3;
    int aRowIn = ((lane >> 3) & 1) * 8 + (lane & 7);
    int aColIn = ((lane >> 3) >> 1) * 4;

    float acc[2][4][4];
    #pragma unroll
    for (int i = 0; i < 2; i++)
        #pragma unroll
        for (int j = 0; j < 4; j++)
            #pragma unroll
            for (int r = 0; r < 4; r++) acc[i][j][r] = 0.f;

    for (int t = 0; t < nTiles; t++) {
        asm volatile("cp.async.wait_group 2;");
        __syncthreads();
        int tn = t + 3;
        if (tn < nTiles) {
            int stg = tn & 3;
            int k0 = tn * 16;
            cpa16(&sA[((stg*128) + aRow)*20 + aColQ],     aPtr + (size_t)aRow * T_ + k0 + aColQ);
            cpa16(&sA[((stg*128) + aRow)*20 + aColQ + 4], aPtr + (size_t)aRow * T_ + k0 + aColQ + 4);
            cpa16(&sB[((stg*16) + bK)*72 + bN], vbase + (size_t)(k0 + bK) * C3_ + bN);
        }
        asm volatile("cp.async.commit_group;");

        int buf = t & 3;
        const float* Ab = sA + buf*128*20;
        const float* Bb = sB + buf*16*72;
        #pragma unroll
        for (int s = 0; s < 2; s++) {
            unsigned af[2][4];
            #pragma unroll
            for (int i = 0; i < 2; i++)
                ldsm4(af[i][0], af[i][1], af[i][2], af[i][3],
                      &Ab[(warpM + i*16 + aRowIn)*20 + s*8 + aColIn]);
            unsigned bf[4][2];
            #pragma unroll
            for (int j = 0; j < 4; j++) {
                int col = warpN + j*8 + g;
                bf[j][0] = __float_as_uint(Bb[(s*8 + tg)*72 + col]);
                bf[j][1] = __float_as_uint(Bb[(s*8 + tg + 4)*72 + col]);
            }
            #pragma unroll
            for (int i = 0; i < 2; i++)
                #pragma unroll
                for (int j = 0; j < 4; j++)
                    mma_tf32(acc[i][j], af[i], bf[j]);
        }
    }

    #pragma unroll
    for (int i = 0; i < 2; i++) {
        int r0 = warpM + i * 16 + g;
        int r1 = r0 + 8;
        #pragma unroll
        for (int j = 0; j < 4; j++) {
            int col = h * HS_ + warpN + j * 8 + tg * 2;
            *(float2*)&O[(size_t)(b * T_ + t0 + r0) * C_ + col] =
                make_float2(rna_tf32(acc[i][j][0]), rna_tf32(acc[i][j][1]));
            *(float2*)&O[(size_t)(b * T_ + t0 + r1) * C_ + col] =
                make_float2(rna_tf32(acc[i][j][2]), rna_tf32(acc[i][j][3]));
        }
    }
}

// ---------------- router (uses exact h2) ----------------
__global__ __launch_bounds__(256) void router_kernel(
    const float* __restrict__ h2,
    const float* __restrict__ wr, const float* __restrict__ br,
    const float* __restrict__ wn, const float* __restrict__ bn,
    const float* __restrict__ noise, const float* __restrict__ temp_p,
    int* __restrict__ cnt, int* __restrict__ tok, float* __restrict__ gw)
{
    int n = blockIdx.x * 8 + (threadIdx.x >> 5);
    if (n >= N_) return;
    int lane = threadIdx.x & 31;
    float ar[E_] = {}, an[E_] = {};
    const float* hp = h2 + (size_t)n * C_;
    for (int c = lane; c < C_; c += 32) {
        float hv = hp[c];
        const float* wrp = wr + c * E_;
        const float* wnp = wn + c * E_;
        #pragma unroll
        for (int e = 0; e < E_; e++) {
            ar[e] = fmaf(hv, wrp[e], ar[e]);
            an[e] = fmaf(hv, wnp[e], an[e]);
        }
    }
    #pragma unroll
    for (int e = 0; e < E_; e++) {
        #pragma unroll
        for (int o = 16; o; o >>= 1) {
            ar[e] += __shfl_down_sync(0xffffffffu, ar[e], o);
            an[e] += __shfl_down_sync(0xffffffffu, an[e], o);
        }
    }
    if (lane == 0) {
        float t = fminf(fmaxf(*temp_p, 0.5f), 2.0f);
        float noisy[E_];
        #pragma unroll
        for (int e = 0; e < E_; e++) {
            float logit = ar[e] + br[e];
            float z = an[e] + bn[e];
            float sp = fmaxf(z, 0.f) + log1pf(expf(-fabsf(z)));
            noisy[e] = logit + t * noise[(size_t)n * E_ + e] * sp;
        }
        int i1 = 0;
        #pragma unroll
        for (int e = 1; e < E_; e++) if (noisy[e] > noisy[i1]) i1 = e;
        int i2 = -1;
        #pragma unroll
        for (int e = 0; e < E_; e++)
            if (e != i1 && (i2 < 0 || noisy[e] > noisy[i2])) i2 = e;
        float m = fmaxf(noisy[i1], noisy[i2]);
        float e1 = __expf(noisy[i1] - m), e2 = __expf(noisy[i2] - m);
        float inv = 1.f / (e1 + e2);
        int p1 = atomicAdd(&cnt[i1], 1); tok[i1 * N_ + p1] = n; gw[i1 * N_ + p1] = e1 * inv;
        int p2 = atomicAdd(&cnt[i2], 1); tok[i2 * N_ + p2] = n; gw[i2 * N_ + p2] = e2 * inv;
    }
}

// ---------------- expert epilogue: out[n] += gate * LN(h2[n] + Y[m]) ----------------
__global__ __launch_bounds__(256) void expert_epi_kernel(
    const float* __restrict__ Y, const float* __restrict__ h2,
    const int* __restrict__ tok, const float* __restrict__ gw,
    const int* __restrict__ cnt,
    const float* __restrict__ lg, const float* __restrict__ lb,
    float* __restrict__ out)
{
    int m = blockIdx.x;
    if (m >= *cnt) return;
    int n = tok[m];
    float g = gw[m];
    const float* yp = Y + (size_t)m * C_;
    const float* hp = h2 + (size_t)n * C_;
    int t = threadIdx.x;
    float z0 = hp[t]       + yp[t];
    float z1 = hp[t + 256] + yp[t + 256];
    float z2 = hp[t + 512] + yp[t + 512];
    float mean = blockReduceSum256(z0 + z1 + z2) * (1.0f / C_);
    float d0 = z0 - mean, d1 = z1 - mean, d2 = z2 - mean;
    float var = blockReduceSum256(d0*d0 + d1*d1 + d2*d2) * (1.0f / C_);
    float rstd = rsqrtf(var + 1e-5f);
    float* op = out + (size_t)n * C_;
    op[t]       += g * (d0 * rstd * lg[t]       + lb[t]);
    op[t + 256] += g * (d1 * rstd * lg[t + 256] + lb[t + 256]);
    op[t + 512] += g * (d2 * rstd * lg[t + 512] + lb[t + 512]);
}

// ---------------- launch ----------------
extern "C" void kernel_launch(void* const* d_in, const int* in_sizes, int n_in,
                              void* d_out, int out_size) {
    const float* x         = (const float*)d_in[0];
    const float* rnoise    = (const float*)d_in[1];
    const float* wq        = (const float*)d_in[2];
    const float* wk        = (const float*)d_in[3];
    const float* wv        = (const float*)d_in[4];
    const float* w_proj    = (const float*)d_in[5];
    const float* b_proj    = (const float*)d_in[6];
    const float* ln1_g     = (const float*)d_in[7];
    const float* ln1_b     = (const float*)d_in[8];
    const float* ln2_g     = (const float*)d_in[9];
    const float* ln2_b     = (const float*)d_in[10];
    const float* w_route   = (const float*)d_in[11];
    const float* b_route   = (const float*)d_in[12];
    const float* w_noise   = (const float*)d_in[13];
    const float* b_noise   = (const float*)d_in[14];
    const float* temp      = (const float*)d_in[15];
    const float* deep_w1   = (const float*)d_in[16];
    const float* deep_b1   = (const float*)d_in[17];
    const float* deep_w2   = (const float*)d_in[18];
    const float* deep_b2   = (const float*)d_in[19];
    const float* deep_w3   = (const float*)d_in[20];
    const float* deep_b3   = (const float*)d_in[21];
    const float* deep_ln_g = (const float*)d_in[22];
    const float* deep_ln_b = (const float*)d_in[23];
    const float* simple_w1   = (const float*)d_in[24];
    const float* simple_b1   = (const float*)d_in[25];
    const float* simple_w2   = (const float*)d_in[26];
    const float* simple_b2   = (const float*)d_in[27];
    const float* simple_ln_g = (const float*)d_in[28];
    const float* simple_ln_b = (const float*)d_in[29];

    float* out = (float*)d_out;

    float *h1, *qkv, *S, *o, *h2, *mid1, *mid2, *Y, *Wqkv, *Wr, *gw;
    int *cnt, *tok;
    cudaGetSymbolAddress((void**)&h1,   g_h1);
    cudaGetSymbolAddress((void**)&qkv,  g_qkv);
    cudaGetSymbolAddress((void**)&S,    g_S);
    cudaGetSymbolAddress((void**)&o,    g_o);
    cudaGetSymbolAddress((void**)&h2,   g_h2);
    cudaGetSymbolAddress((void**)&mid1, g_mid1);
    cudaGetSymbolAddress((void**)&mid2, g_mid2);
    cudaGetSymbolAddress((void**)&Y,    g_Y);
    cudaGetSymbolAddress((void**)&Wqkv, g_Wqkv);
    cudaGetSymbolAddress((void**)&Wr,   g_Wr);
    cudaGetSymbolAddress((void**)&cnt,  g_cnt);
    cudaGetSymbolAddress((void**)&tok,  g_tok);
    cudaGetSymbolAddress((void**)&gw,   g_gw);

    // raise dynamic smem limits (idempotent)
    cudaFuncSetAttribute((const void*)tgemm_k<false,0,false,true>,  cudaFuncAttributeMaxDynamicSharedMemorySize, TG_SMEM);
    cudaFuncSetAttribute((const void*)tgemm_k<false,0,true,false>,  cudaFuncAttributeMaxDynamicSharedMemorySize, TG_SMEM);
    cudaFuncSetAttribute((const void*)tgemm_k<true,1,false,true>,   cudaFuncAttributeMaxDynamicSharedMemorySize, TG_SMEM);
    cudaFuncSetAttribute((const void*)tgemm_k<false,1,false,true>,  cudaFuncAttributeMaxDynamicSharedMemorySize, TG_SMEM);
    cudaFuncSetAttribute((const void*)tgemm_k<false,0,false,false>, cudaFuncAttributeMaxDynamicSharedMemorySize, TG_SMEM);
    cudaFuncSetAttribute((const void*)attn_scores_tc, cudaFuncAttributeMaxDynamicSharedMemorySize, SC_SMEM);
    cudaFuncSetAttribute((const void*)attn_pv_tc,     cudaFuncAttributeMaxDynamicSharedMemorySize, PV_SMEM);

    zero_cnt_kernel<<<1, 32>>>(cnt);
    pack_wqkv_kernel<<<(C_ * C3_ + 255) / 256, 256>>>(wq, wk, wv);

    // pre-round weights to tf32
    round_copy_kernel<<<PW_SZ/1024,  256>>>(w_proj,    Wr + PW_OFF,  PW_SZ/4);
    round_copy_kernel<<<DW1_SZ/1024, 256>>>(deep_w1,   Wr + DW1_OFF, DW1_SZ/4);
    round_copy_kernel<<<DW2_SZ/1024, 256>>>(deep_w2,   Wr + DW2_OFF, DW2_SZ/4);
    round_copy_kernel<<<DW3_SZ/1024, 256>>>(deep_w3,   Wr + DW3_OFF, DW3_SZ/4);
    round_copy_kernel<<<SW1_SZ/1024, 256>>>(simple_w1, Wr + SW1_OFF, SW1_SZ/4);
    round_copy_kernel<<<SW2_SZ/1024, 256>>>(simple_w2, Wr + SW2_OFF, SW2_SZ/4);

    // ln1 -> h1 (rounded) ; qkv = h1 @ Wqkv (rounded out)
    ln_kernel<true><<<N_, 256>>>(x, ln1_g, ln1_b, h1, nullptr);
    tgemm_k<false, 0, false, true><<<dim3(C3_ / 128, N_ / 128), 256, TG_SMEM>>>(
        h1, C_, Wqkv, nullptr, nullptr, qkv, C3_, N_, C3_, C_, nullptr, nullptr);

    // attention (tensor core)
    attn_scores_tc<<<dim3(T_ / 128, T_ / 128, BH_), 256, SC_SMEM>>>(qkv, S);
    softmax_causal_kernel<<<BH_ * T_, 128>>>(S);
    attn_pv_tc<<<dim3(T_ / 128, BH_), 256, PV_SMEM>>>(qkv, S, o);

    // out = x + o @ w_proj + b_proj
    tgemm_k<false, 0, true, false><<<dim3(C_ / 128, N_ / 128), 256, TG_SMEM>>>(
        o, C_, Wr + PW_OFF, b_proj, x, out, C_, N_, C_, C_, nullptr, nullptr);

    // ln2 -> h2 (exact) + h2r (rounded, reuses h1 buffer) ; router
    ln_kernel<false><<<N_, 256>>>(out, ln2_g, ln2_b, h2, h1);
    router_kernel<<<N_ / 8, 256>>>(h2, w_route, b_route, w_noise, b_noise,
                                   rnoise, temp, cnt, tok, gw);

    // deep experts (0..1)
    for (int e = 0; e < 2; e++) {
        const int*   ce = cnt + e;
        const int*   te = tok + e * N_;
        const float* ge = gw + e * N_;
        tgemm_k<true, 1, false, true><<<dim3(F_ / 128, N_ / 128), 256, TG_SMEM>>>(
            h1, C_, Wr + DW1_OFF + (size_t)e * C_ * F_, deep_b1 + (size_t)e * F_,
            nullptr, mid1, F_, N_, F_, C_, te, ce);
        tgemm_k<false, 1, false, true><<<dim3(F_ / 128, N_ / 128), 256, TG_SMEM>>>(
            mid1, F_, Wr + DW2_OFF + (size_t)e * F_ * F_, deep_b2 + (size_t)e * F_,
            nullptr, mid2, F_, N_, F_, F_, nullptr, ce);
        tgemm_k<false, 0, false, false><<<dim3(C_ / 128, N_ / 128), 256, TG_SMEM>>>(
            mid2, F_, Wr + DW3_OFF + (size_t)e * F_ * C_, deep_b3 + (size_t)e * C_,
            nullptr, Y, C_, N_, C_, F_, nullptr, ce);
        expert_epi_kernel<<<N_, 256>>>(Y, h2, te, ge, ce,
                                       deep_ln_g + (size_t)e * C_,
                                       deep_ln_b + (size_t)e * C_, out);
    }

    // simple experts (2..7)
    for (int e = 0; e < 6; e++) {
        int ee = 2 + e;
        const int*   ce = cnt + ee;
        const int*   te = tok + ee * N_;
        const float* ge = gw + ee * N_;
        tgemm_k<true, 1, false, true><<<dim3(F_ / 128, N_ / 128), 256, TG_SMEM>>>(
            h1, C_, Wr + SW1_OFF + (size_t)e * C_ * F_, simple_b1 + (size_t)e * F_,
            nullptr, mid1, F_, N_, F_, C_, te, ce);
        tgemm_k<false, 0, false, false><<<dim3(C_ / 128, N_ / 128), 256, TG_SMEM>>>(
            mid1, F_, Wr + SW2_OFF + (size_t)e * F_ * C_, simple_b2 + (size_t)e * C_,
            nullptr, Y, C_, N_, C_, F_, nullptr, ce);
        expert_epi_kernel<<<N_, 256>>>(Y, h2, te, ge, ce,
                                       simple_ln_g + (size_t)e * C_,
                                       simple_ln_b + (size_t)e * C_, out);
    }
}

// round 14
// speedup vs baseline: 1.4517x; 1.2412x over previous
#include <cuda_runtime.h>
#include <math.h>

// ---------------- problem constants ----------------
#define B_   8
#define T_   1024
#define C_   768
#define H_   12
#define HS_  64
#define E_   8
#define F_   3072
#define N_   (B_*T_)     // 8192 tokens
#define BH_  (B_*H_)     // 96
#define C3_  (3*C_)      // 2304

// dynamic smem sizes
#define TG_SMEM  (4*(128*20 + 16*136)*4)     // 75776
#define SC_SMEM  ((128*68 + 64*136)*4)       // 69632
#define PV_SMEM  (4*(128*20 + 16*72)*4)      // 59392

// ---------------- scratch (device globals; no allocation) ----------------
__device__ float g_h1  [N_*C_];               // h1 (rounded), later h2r (rounded)
__device__ float g_qkv [N_*C3_];
__device__ float g_S   [(size_t)BH_*T_*T_];
__device__ float g_o   [N_*C_];
__device__ float g_h2  [N_*C_];               // exact h2
__device__ float g_mid1[(size_t)E_*N_*F_];    // per-expert slabs (805 MB)
__device__ float g_mid2[(size_t)2*N_*F_];     // deep mid2 slabs
__device__ float g_Yc  [(size_t)E_*N_*C_];    // per-slot expert outputs
__device__ float g_Wqkv[C_*C3_];
__device__ int   g_cnt [E_];
__device__ int   g_tok [E_*N_];
__device__ float g_gw  [E_*N_];
__device__ int   g_slot[2*N_];

// ---------------- helpers ----------------
__device__ __forceinline__ float gelu_f(float z) {
    return 0.5f * z * (1.0f + erff(z * 0.70710678118654752440f));
}

__device__ __forceinline__ float rna_tf32(float f) {
    unsigned r;
    asm("cvt.rna.tf32.f32 %0, %1;" : "=r"(r) : "f"(f));
    return __uint_as_float(r);
}

__device__ __forceinline__ void cpa16(void* smem_dst, const void* gsrc) {
    unsigned d = (unsigned)__cvta_generic_to_shared(smem_dst);
    asm volatile("cp.async.cg.shared.global [%0], [%1], 16;" :: "r"(d), "l"(gsrc));
}

__device__ __forceinline__ void ldsm4(unsigned &r0, unsigned &r1, unsigned &r2, unsigned &r3,
                                      const void* p) {
    unsigned addr = (unsigned)__cvta_generic_to_shared(p);
    asm volatile("ldmatrix.sync.aligned.m8n8.x4.shared.b16 {%0,%1,%2,%3}, [%4];"
        : "=r"(r0), "=r"(r1), "=r"(r2), "=r"(r3) : "r"(addr));
}

__device__ __forceinline__ void mma_tf32(float* c, const unsigned* a, const unsigned* b) {
    asm volatile("mma.sync.aligned.m16n8k8.row.col.f32.tf32.tf32.f32 "
        "{%0,%1,%2,%3}, {%4,%5,%6,%7}, {%8,%9}, {%0,%1,%2,%3};"
        : "+f"(c[0]), "+f"(c[1]), "+f"(c[2]), "+f"(c[3])
        : "r"(a[0]), "r"(a[1]), "r"(a[2]), "r"(a[3]), "r"(b[0]), "r"(b[1]));
}

__device__ __forceinline__ float blockReduceSum256(float v) {
    __shared__ float sh[8];
    int lane = threadIdx.x & 31, w = threadIdx.x >> 5;
    #pragma unroll
    for (int o = 16; o; o >>= 1) v += __shfl_down_sync(0xffffffffu, v, o);
    if (lane == 0) sh[w] = v;
    __syncthreads();
    float r;
    if (w == 0) {
        float t = (lane < 8) ? sh[lane] : 0.f;
        #pragma unroll
        for (int o = 4; o; o >>= 1) t += __shfl_down_sync(0xffffffffu, t, o);
        if (lane == 0) sh[0] = t;
    }
    __syncthreads();
    r = sh[0];
    __syncthreads();
    return r;
}

// ---------------- small setup kernels ----------------
__global__ void zero_cnt_kernel(int* cnt) {
    if (threadIdx.x < E_) cnt[threadIdx.x] = 0;
}

// pack wq,wk,wv (H,C,HS) -> Wqkv[C][3C], rounded
__global__ void pack_wqkv_kernel(const float* __restrict__ wq,
                                 const float* __restrict__ wk,
                                 const float* __restrict__ wv) {
    int idx = blockIdx.x * 256 + threadIdx.x;
    if (idx >= C_ * C3_) return;
    int c   = idx / C3_;
    int col = idx - c * C3_;
    int which = col / C_;
    int rem   = col - which * C_;
    int h = rem / HS_;
    int d = rem - h * HS_;
    const float* w = (which == 0) ? wq : ((which == 1) ? wk : wv);
    g_Wqkv[idx] = rna_tf32(w[(h * C_ + c) * HS_ + d]);
}

// LayerNorm; ROUND_MAIN rounds main output; outR (optional) gets rounded copy
template<bool ROUND_MAIN>
__global__ __launch_bounds__(256) void ln_kernel(const float* __restrict__ in,
                                                 const float* __restrict__ g,
                                                 const float* __restrict__ b,
                                                 float* __restrict__ out,
                                                 float* __restrict__ outR) {
    int row = blockIdx.x;
    const float* p = in + (size_t)row * C_;
    int t = threadIdx.x;
    float x0 = p[t], x1 = p[t + 256], x2 = p[t + 512];
    float mean = blockReduceSum256(x0 + x1 + x2) * (1.0f / C_);
    float d0 = x0 - mean, d1 = x1 - mean, d2 = x2 - mean;
    float var = blockReduceSum256(d0*d0 + d1*d1 + d2*d2) * (1.0f / C_);
    float rstd = rsqrtf(var + 1e-5f);
    float v0 = d0 * rstd * g[t]       + b[t];
    float v1 = d1 * rstd * g[t + 256] + b[t + 256];
    float v2 = d2 * rstd * g[t + 512] + b[t + 512];
    float* o = out + (size_t)row * C_;
    if (ROUND_MAIN) {
        o[t] = rna_tf32(v0); o[t+256] = rna_tf32(v1); o[t+512] = rna_tf32(v2);
    } else {
        o[t] = v0; o[t+256] = v1; o[t+512] = v2;
    }
    if (outR) {
        float* r = outR + (size_t)row * C_;
        r[t] = rna_tf32(v0); r[t+256] = rna_tf32(v1); r[t+512] = rna_tf32(v2);
    }
}

// ---------------- shared tf32 GEMM body (4-stage cp.async) ----------------
// Block 128x128x16, 8 warps 2x4, warp tile 64x32. Nn%128==0, Kk%16==0.
// RB: round B elements (raw fp32 weights) to tf32 at fragment load.
template<bool GATHER, int ACT, bool RESID, bool ROUND, bool RB>
__device__ __forceinline__ void gemm_body(
    const float* __restrict__ A, int lda,
    const float* __restrict__ Bm,
    const float* __restrict__ bias,
    const float* __restrict__ resid,
    float* __restrict__ Cm, int ldc,
    int M, int Nn, int Kk,
    const int* __restrict__ rows,
    int m0, int n0)
{
    extern __shared__ float sm[];
    float* sA = sm;                 // [4][128][20]
    float* sB = sm + 4*128*20;      // [4][16][136]
    __shared__ int rIdx[128];

    int tid = threadIdx.x;
    if (GATHER) {
        if (tid < 128) { int m = m0 + tid; rIdx[tid] = rows[(m < M) ? m : (M - 1)]; }
        __syncthreads();
    }

    int aRow = tid & 127;
    int aCol = (tid >> 7) * 4;       // {0,4}; second load at +8
    int aSrcRow;
    if (GATHER) aSrcRow = rIdx[aRow];
    else { int gm = m0 + aRow; aSrcRow = (gm < M) ? gm : (M - 1); }
    const float* aPtr = A + (size_t)aSrcRow * lda;
    int bK = tid >> 4;
    int bN = (tid & 15) * 4;
    const float* bPtr = Bm + (size_t)bK * Nn + n0;

    int nTiles = Kk / 16;

    #pragma unroll
    for (int s = 0; s < 3; s++) {
        int k0 = s * 16;
        cpa16(&sA[((s*128) + aRow)*20 + aCol],     aPtr + k0 + aCol);
        cpa16(&sA[((s*128) + aRow)*20 + aCol + 8], aPtr + k0 + aCol + 8);
        const float* bp = bPtr + (size_t)k0 * Nn;
        cpa16(&sB[((s*16) + bK)*136 + bN],      bp + bN);
        cpa16(&sB[((s*16) + bK)*136 + bN + 64], bp + bN + 64);
        asm volatile("cp.async.commit_group;");
    }

    int wid = tid >> 5, lane = tid & 31;
    int warpM = (wid >> 2) * 64;
    int warpN = (wid & 3) * 32;
    int g  = lane >> 2;
    int tg = lane & 3;
    int aRowIn = ((lane >> 3) & 1) * 8 + (lane & 7);
    int aColIn = ((lane >> 3) >> 1) * 4;

    float acc[4][4][4];
    #pragma unroll
    for (int i = 0; i < 4; i++)
        #pragma unroll
        for (int j = 0; j < 4; j++)
            #pragma unroll
            for (int r = 0; r < 4; r++) acc[i][j][r] = 0.f;

    for (int t = 0; t < nTiles; t++) {
        asm volatile("cp.async.wait_group 2;");
        __syncthreads();
        int tn = t + 3;
        if (tn < nTiles) {
            int stg = tn & 3;
            int k0 = tn * 16;
            cpa16(&sA[((stg*128) + aRow)*20 + aCol],     aPtr + k0 + aCol);
            cpa16(&sA[((stg*128) + aRow)*20 + aCol + 8], aPtr + k0 + aCol + 8);
            const float* bp = bPtr + (size_t)k0 * Nn;
            cpa16(&sB[((stg*16) + bK)*136 + bN],      bp + bN);
            cpa16(&sB[((stg*16) + bK)*136 + bN + 64], bp + bN + 64);
        }
        asm volatile("cp.async.commit_group;");

        int buf = t & 3;
        const float* Ab = sA + buf*128*20;
        const float* Bb = sB + buf*16*136;
        #pragma unroll
        for (int s = 0; s < 2; s++) {
            unsigned af[4][4];
            #pragma unroll
            for (int i = 0; i < 4; i++)
                ldsm4(af[i][0], af[i][1], af[i][2], af[i][3],
                      &Ab[(warpM + i*16 + aRowIn)*20 + s*8 + aColIn]);
            unsigned bf[4][2];
            #pragma unroll
            for (int j = 0; j < 4; j++) {
                int col = warpN + j*8 + g;
                float b0 = Bb[(s*8 + tg)*136 + col];
                float b1 = Bb[(s*8 + tg + 4)*136 + col];
                if (RB) { b0 = rna_tf32(b0); b1 = rna_tf32(b1); }
                bf[j][0] = __float_as_uint(b0);
                bf[j][1] = __float_as_uint(b1);
            }
            #pragma unroll
            for (int i = 0; i < 4; i++)
                #pragma unroll
                for (int j = 0; j < 4; j++)
                    mma_tf32(acc[i][j], af[i], bf[j]);
        }
    }

    #pragma unroll
    for (int i = 0; i < 4; i++) {
        int r0 = m0 + warpM + i * 16 + g;
        int r1 = r0 + 8;
        #pragma unroll
        for (int j = 0; j < 4; j++) {
            int col = n0 + warpN + j * 8 + tg * 2;
            float b0 = 0.f, b1 = 0.f;
            if (bias) { b0 = bias[col]; b1 = bias[col + 1]; }
            if (r0 < M) {
                float v0 = acc[i][j][0] + b0;
                float v1 = acc[i][j][1] + b1;
                if (ACT == 1) { v0 = gelu_f(v0); v1 = gelu_f(v1); }
                if (RESID) {
                    v0 += resid[(size_t)r0 * ldc + col];
                    v1 += resid[(size_t)r0 * ldc + col + 1];
                }
                if (ROUND) { v0 = rna_tf32(v0); v1 = rna_tf32(v1); }
                *(float2*)&Cm[(size_t)r0 * ldc + col] = make_float2(v0, v1);
            }
            if (r1 < M) {
                float v2 = acc[i][j][2] + b0;
                float v3 = acc[i][j][3] + b1;
                if (ACT == 1) { v2 = gelu_f(v2); v3 = gelu_f(v3); }
                if (RESID) {
                    v2 += resid[(size_t)r1 * ldc + col];
                    v3 += resid[(size_t)r1 * ldc + col + 1];
                }
                if (ROUND) { v2 = rna_tf32(v2); v3 = rna_tf32(v3); }
                *(float2*)&Cm[(size_t)r1 * ldc + col] = make_float2(v2, v3);
            }
        }
    }
}

// plain GEMM wrapper (QKV, proj)
template<int ACT, bool RESID, bool ROUND, bool RB>
__global__ __launch_bounds__(256) void tgemm_k(
    const float* __restrict__ A, int lda,
    const float* __restrict__ Bm,
    const float* __restrict__ bias,
    const float* __restrict__ resid,
    float* __restrict__ Cm, int ldc,
    int M, int Nn, int Kk)
{
    int m0 = blockIdx.y * 128;
    if (m0 >= M) return;
    gemm_body<false, ACT, RESID, ROUND, RB>(A, lda, Bm, bias, resid, Cm, ldc,
                                            M, Nn, Kk, nullptr, m0, blockIdx.x * 128);
}

// ---------------- batched expert GEMMs (blockIdx.z = expert) ----------------
// MODE 0: w1    : gather h (C->F), gelu, round;  W = deep_w1|simple_w1
// MODE 1: w2d   : mid1[z] (F->F), gelu, round;   W = deep_w2 (z in 0..1)
// MODE 2: final : deep: mid2[z] (F->C) W=deep_w3 ; simple: mid1[z] (F->C) W=simple_w2
template<int MODE>
__global__ __launch_bounds__(256) void egemm_k(
    const float* __restrict__ hA,
    const float* __restrict__ mid1,
    const float* __restrict__ mid2,
    const float* __restrict__ dW, const float* __restrict__ sW,
    const float* __restrict__ dBias, const float* __restrict__ sBias,
    float* __restrict__ Cout,
    const int* __restrict__ tok, const int* __restrict__ cnt)
{
    int z = blockIdx.z;
    int M = cnt[z];
    int m0 = blockIdx.y * 128;
    if (m0 >= M) return;
    int n0 = blockIdx.x * 128;
    bool deep = (MODE == 1) ? true : (z < 2);

    if (MODE == 0) {
        const float* W  = deep ? dW + (size_t)z * C_ * F_ : sW + (size_t)(z - 2) * C_ * F_;
        const float* bs = deep ? dBias + (size_t)z * F_   : sBias + (size_t)(z - 2) * F_;
        float* Cm = Cout + (size_t)z * N_ * F_;
        gemm_body<true, 1, false, true, true>(hA, C_, W, bs, nullptr, Cm, F_,
                                              M, F_, C_, tok + (size_t)z * N_, m0, n0);
    } else if (MODE == 1) {
        const float* A  = mid1 + (size_t)z * N_ * F_;
        const float* W  = dW + (size_t)z * F_ * F_;
        const float* bs = dBias + (size_t)z * F_;
        float* Cm = Cout + (size_t)z * N_ * F_;
        gemm_body<false, 1, false, true, true>(A, F_, W, bs, nullptr, Cm, F_,
                                               M, F_, F_, nullptr, m0, n0);
    } else {
        const float* A  = deep ? mid2 + (size_t)z * N_ * F_ : mid1 + (size_t)z * N_ * F_;
        const float* W  = deep ? dW + (size_t)z * F_ * C_   : sW + (size_t)(z - 2) * F_ * C_;
        const float* bs = deep ? dBias + (size_t)z * C_     : sBias + (size_t)(z - 2) * C_;
        float* Cm = Cout + (size_t)z * N_ * C_;
        gemm_body<false, 0, false, false, true>(A, F_, W, bs, nullptr, Cm, C_,
                                                M, C_, F_, nullptr, m0, n0);
    }
}

// ---------------- attention scores (tf32 mma) ----------------
__global__ __launch_bounds__(256) void attn_scores_tc(const float* __restrict__ qkv,
                                                      float* __restrict__ S) {
    int t0 = blockIdx.y * 128, s0 = blockIdx.x * 128;
    if (s0 > t0) return;
    int bh = blockIdx.z;
    int b = bh / H_, h = bh - b * H_;

    extern __shared__ float sm[];
    float* Qs = sm;              // [128][68]
    float* Ks = sm + 128*68;     // [64][136]  ([d][s])
    int tid = threadIdx.x;

    const float* qbase = qkv + (size_t)(b * T_ + t0) * C3_ + h * HS_;
    #pragma unroll
    for (int l = 0; l < 8; l++) {
        int idx = tid + l * 256;
        int r = idx >> 4, q = idx & 15;
        cpa16(&Qs[r*68 + q*4], qbase + (size_t)r * C3_ + q * 4);
    }
    asm volatile("cp.async.commit_group;");

    const float* kbase = qkv + (size_t)(b * T_ + s0) * C3_ + C_ + h * HS_;
    #pragma unroll
    for (int l = 0; l < 8; l++) {
        int idx = tid + l * 256;
        int s = idx & 127, q = idx >> 7;
        float4 v = *(const float4*)(kbase + (size_t)s * C3_ + q * 4);
        Ks[(q*4+0)*136 + s] = v.x;
        Ks[(q*4+1)*136 + s] = v.y;
        Ks[(q*4+2)*136 + s] = v.z;
        Ks[(q*4+3)*136 + s] = v.w;
    }
    asm volatile("cp.async.wait_group 0;");
    __syncthreads();

    int wid = tid >> 5, lane = tid & 31;
    int warpM = (wid >> 2) * 64, warpN = (wid & 3) * 32;
    int g = lane >> 2, tg = lane & 3;
    int aRowIn = ((lane >> 3) & 1) * 8 + (lane & 7);
    int aColIn = ((lane >> 3) >> 1) * 4;

    float acc[4][4][4];
    #pragma unroll
    for (int i = 0; i < 4; i++)
        #pragma unroll
        for (int j = 0; j < 4; j++)
            #pragma unroll
            for (int r = 0; r < 4; r++) acc[i][j][r] = 0.f;

    #pragma unroll
    for (int ks = 0; ks < 8; ks++) {
        unsigned af[4][4];
        #pragma unroll
        for (int i = 0; i < 4; i++)
            ldsm4(af[i][0], af[i][1], af[i][2], af[i][3],
                  &Qs[(warpM + i*16 + aRowIn)*68 + ks*8 + aColIn]);
        unsigned bf[4][2];
        #pragma unroll
        for (int j = 0; j < 4; j++) {
            int col = warpN + j*8 + g;
            bf[j][0] = __float_as_uint(Ks[(ks*8 + tg)*136 + col]);
            bf[j][1] = __float_as_uint(Ks[(ks*8 + tg + 4)*136 + col]);
        }
        #pragma unroll
        for (int i = 0; i < 4; i++)
            #pragma unroll
            for (int j = 0; j < 4; j++)
                mma_tf32(acc[i][j], af[i], bf[j]);
    }

    const float scale = 0.03608439182435161f;   // 768^-0.5
    float* op = S + ((size_t)bh * T_ + t0) * T_ + s0;
    #pragma unroll
    for (int i = 0; i < 4; i++) {
        int r0 = warpM + i * 16 + g;
        int r1 = r0 + 8;
        #pragma unroll
        for (int j = 0; j < 4; j++) {
            int col = warpN + j * 8 + tg * 2;
            *(float2*)&op[(size_t)r0 * T_ + col] =
                make_float2(acc[i][j][0] * scale, acc[i][j][1] * scale);
            *(float2*)&op[(size_t)r1 * T_ + col] =
                make_float2(acc[i][j][2] * scale, acc[i][j][3] * scale);
        }
    }
}

// ---------------- causal softmax (in place, rounds P, zero-fill to tile edge) ----------------
__global__ __launch_bounds__(128) void softmax_causal_kernel(float* __restrict__ S) {
    int row = blockIdx.x;
    int t = row & (T_ - 1);
    float* p = S + (size_t)row * T_;
    int len = t + 1;
    int end = ((t >> 7) + 1) << 7;   // end of diagonal 128-tile (PV never reads past it)
    int tid = threadIdx.x;
    __shared__ float sh[4];

    float mx = -1e30f;
    for (int s = tid; s < len; s += 128) mx = fmaxf(mx, p[s]);
    #pragma unroll
    for (int o = 16; o; o >>= 1) mx = fmaxf(mx, __shfl_down_sync(0xffffffffu, mx, o));
    if ((tid & 31) == 0) sh[tid >> 5] = mx;
    __syncthreads();
    mx = fmaxf(fmaxf(sh[0], sh[1]), fmaxf(sh[2], sh[3]));
    __syncthreads();

    float sum = 0.f;
    for (int s = tid; s < len; s += 128) { float e = __expf(p[s] - mx); p[s] = e; sum += e; }
    #pragma unroll
    for (int o = 16; o; o >>= 1) sum += __shfl_down_sync(0xffffffffu, sum, o);
    if ((tid & 31) == 0) sh[tid >> 5] = sum;
    __syncthreads();
    sum = sh[0] + sh[1] + sh[2] + sh[3];
    float inv = 1.f / sum;
    for (int s = tid; s < len; s += 128) p[s] = rna_tf32(p[s] * inv);
    for (int s = len + tid; s < end; s += 128) p[s] = 0.f;
}

// ---------------- PV (tf32 mma, cp.async pipelined) ----------------
__global__ __launch_bounds__(256) void attn_pv_tc(const float* __restrict__ qkv,
                                                  const float* __restrict__ P,
                                                  float* __restrict__ O) {
    int t0 = blockIdx.x * 128;
    int bh = blockIdx.y;
    int b = bh / H_, h = bh - b * H_;

    extern __shared__ float sm[];
    float* sA = sm;                 // [4][128][20]
    float* sB = sm + 4*128*20;      // [4][16][72]

    int tid = threadIdx.x;
    const float* aPtr = P + ((size_t)bh * T_ + t0) * T_;
    const float* vbase = qkv + (size_t)(b * T_) * C3_ + 2 * C_ + h * HS_;

    int aRow = tid & 127;
    int aColQ = (tid >> 7) * 8;
    int bK = tid >> 4;
    int bN = (tid & 15) * 4;

    int nTiles = (t0 + 128) / 16;

    #pragma unroll
    for (int s = 0; s < 3; s++) {
        int k0 = s * 16;
        cpa16(&sA[((s*128) + aRow)*20 + aColQ],     aPtr + (size_t)aRow * T_ + k0 + aColQ);
        cpa16(&sA[((s*128) + aRow)*20 + aColQ + 4], aPtr + (size_t)aRow * T_ + k0 + aColQ + 4);
        cpa16(&sB[((s*16) + bK)*72 + bN], vbase + (size_t)(k0 + bK) * C3_ + bN);
        asm volatile("cp.async.commit_group;");
    }

    int wid = tid >> 5, lane = tid & 31;
    int warpM = (wid >> 1) * 32;
    int warpN = (wid & 1) * 32;
    int g = lane >> 2, tg = lane & 3;
    int aRowIn = ((lane >> 3) & 1) * 8 + (lane & 7);
    int aColIn = ((lane >> 3) >> 1) * 4;

    float acc[2][4][4];
    #pragma unroll
    for (int i = 0; i < 2; i++)
        #pragma unroll
        for (int j = 0; j < 4; j++)
            #pragma unroll
            for (int r = 0; r < 4; r++) acc[i][j][r] = 0.f;

    for (int t = 0; t < nTiles; t++) {
        asm volatile("cp.async.wait_group 2;");
        __syncthreads();
        int tn = t + 3;
        if (tn < nTiles) {
            int stg = tn & 3;
            int k0 = tn * 16;
            cpa16(&sA[((stg*128) + aRow)*20 + aColQ],     aPtr + (size_t)aRow * T_ + k0 + aColQ);
            cpa16(&sA[((stg*128) + aRow)*20 + aColQ + 4], aPtr + (size_t)aRow * T_ + k0 + aColQ + 4);
            cpa16(&sB[((stg*16) + bK)*72 + bN], vbase + (size_t)(k0 + bK) * C3_ + bN);
        }
        asm volatile("cp.async.commit_group;");

        int buf = t & 3;
        const float* Ab = sA + buf*128*20;
        const float* Bb = sB + buf*16*72;
        #pragma unroll
        for (int s = 0; s < 2; s++) {
            unsigned af[2][4];
            #pragma unroll
            for (int i = 0; i < 2; i++)
                ldsm4(af[i][0], af[i][1], af[i][2], af[i][3],
                      &Ab[(warpM + i*16 + aRowIn)*20 + s*8 + aColIn]);
            unsigned bf[4][2];
            #pragma unroll
            for (int j = 0; j < 4; j++) {
                int col = warpN + j*8 + g;
                bf[j][0] = __float_as_uint(Bb[(s*8 + tg)*72 + col]);
                bf[j][1] = __float_as_uint(Bb[(s*8 + tg + 4)*72 + col]);
            }
            #pragma unroll
            for (int i = 0; i < 2; i++)
                #pragma unroll
                for (int j = 0; j < 4; j++)
                    mma_tf32(acc[i][j], af[i], bf[j]);
        }
    }

    #pragma unroll
    for (int i = 0; i < 2; i++) {
        int r0 = warpM + i * 16 + g;
        int r1 = r0 + 8;
        #pragma unroll
        for (int j = 0; j < 4; j++) {
            int col = h * HS_ + warpN + j * 8 + tg * 2;
            *(float2*)&O[(size_t)(b * T_ + t0 + r0) * C_ + col] =
                make_float2(rna_tf32(acc[i][j][0]), rna_tf32(acc[i][j][1]));
            *(float2*)&O[(size_t)(b * T_ + t0 + r1) * C_ + col] =
                make_float2(rna_tf32(acc[i][j][2]), rna_tf32(acc[i][j][3]));
        }
    }
}

// ---------------- router: noisy top-2 + assignment + slot table ----------------
__global__ __launch_bounds__(256) void router_kernel(
    const float* __restrict__ h2,
    const float* __restrict__ wr, const float* __restrict__ br,
    const float* __restrict__ wn, const float* __restrict__ bn,
    const float* __restrict__ noise, const float* __restrict__ temp_p,
    int* __restrict__ cnt, int* __restrict__ tok, float* __restrict__ gw,
    int* __restrict__ slot)
{
    int n = blockIdx.x * 8 + (threadIdx.x >> 5);
    if (n >= N_) return;
    int lane = threadIdx.x & 31;
    float ar[E_] = {}, an[E_] = {};
    const float* hp = h2 + (size_t)n * C_;
    for (int c = lane; c < C_; c += 32) {
        float hv = hp[c];
        const float* wrp = wr + c * E_;
        const float* wnp = wn + c * E_;
        #pragma unroll
        for (int e = 0; e < E_; e++) {
            ar[e] = fmaf(hv, wrp[e], ar[e]);
            an[e] = fmaf(hv, wnp[e], an[e]);
        }
    }
    #pragma unroll
    for (int e = 0; e < E_; e++) {
        #pragma unroll
        for (int o = 16; o; o >>= 1) {
            ar[e] += __shfl_down_sync(0xffffffffu, ar[e], o);
            an[e] += __shfl_down_sync(0xffffffffu, an[e], o);
        }
    }
    if (lane == 0) {
        float t = fminf(fmaxf(*temp_p, 0.5f), 2.0f);
        float noisy[E_];
        #pragma unroll
        for (int e = 0; e < E_; e++) {
            float logit = ar[e] + br[e];
            float z = an[e] + bn[e];
            float sp = fmaxf(z, 0.f) + log1pf(expf(-fabsf(z)));
            noisy[e] = logit + t * noise[(size_t)n * E_ + e] * sp;
        }
        int i1 = 0;
        #pragma unroll
        for (int e = 1; e < E_; e++) if (noisy[e] > noisy[i1]) i1 = e;
        int i2 = -1;
        #pragma unroll
        for (int e = 0; e < E_; e++)
            if (e != i1 && (i2 < 0 || noisy[e] > noisy[i2])) i2 = e;
        float m = fmaxf(noisy[i1], noisy[i2]);
        float e1 = __expf(noisy[i1] - m), e2 = __expf(noisy[i2] - m);
        float inv = 1.f / (e1 + e2);
        int p1 = atomicAdd(&cnt[i1], 1); tok[i1 * N_ + p1] = n; gw[i1 * N_ + p1] = e1 * inv;
        int p2 = atomicAdd(&cnt[i2], 1); tok[i2 * N_ + p2] = n; gw[i2 * N_ + p2] = e2 * inv;
        slot[2 * n]     = i1 * N_ + p1;
        slot[2 * n + 1] = i2 * N_ + p2;
    }
}

// ---------------- batched expert epilogue: Yc[z][m] = gate * LN(h2[n] + Yc[z][m]) ----------------
__global__ __launch_bounds__(256) void expert_epi_batched(
    float* __restrict__ Yc, const float* __restrict__ h2,
    const int* __restrict__ tok, const float* __restrict__ gw,
    const int* __restrict__ cnt,
    const float* __restrict__ dlg, const float* __restrict__ dlb,
    const float* __restrict__ slg, const float* __restrict__ slb)
{
    int z = blockIdx.y;
    int m = blockIdx.x;
    if (m >= cnt[z]) return;
    bool deep = z < 2;
    const float* lg = deep ? dlg + (size_t)z * C_ : slg + (size_t)(z - 2) * C_;
    const float* lb = deep ? dlb + (size_t)z * C_ : slb + (size_t)(z - 2) * C_;
    int n = tok[z * N_ + m];
    float g = gw[z * N_ + m];
    float* yp = Yc + ((size_t)z * N_ + m) * C_;
    const float* hp = h2 + (size_t)n * C_;
    int t = threadIdx.x;
    float z0 = hp[t]       + yp[t];
    float z1 = hp[t + 256] + yp[t + 256];
    float z2 = hp[t + 512] + yp[t + 512];
    float mean = blockReduceSum256(z0 + z1 + z2) * (1.0f / C_);
    float d0 = z0 - mean, d1 = z1 - mean, d2 = z2 - mean;
    float var = blockReduceSum256(d0*d0 + d1*d1 + d2*d2) * (1.0f / C_);
    float rstd = rsqrtf(var + 1e-5f);
    yp[t]       = g * (d0 * rstd * lg[t]       + lb[t]);
    yp[t + 256] = g * (d1 * rstd * lg[t + 256] + lb[t + 256]);
    yp[t + 512] = g * (d2 * rstd * lg[t + 512] + lb[t + 512]);
}

// ---------------- final combine: out[n] += Yc[slot0] + Yc[slot1] ----------------
__global__ __launch_bounds__(256) void combine_kernel(
    const float* __restrict__ Yc, const int* __restrict__ slot,
    float* __restrict__ out)
{
    int n = blockIdx.x;
    const float* a = Yc + (size_t)slot[2 * n] * C_;
    const float* b = Yc + (size_t)slot[2 * n + 1] * C_;
    float* op = out + (size_t)n * C_;
    int t = threadIdx.x;
    op[t]       += a[t]       + b[t];
    op[t + 256] += a[t + 256] + b[t + 256];
    op[t + 512] += a[t + 512] + b[t + 512];
}

// ---------------- launch ----------------
extern "C" void kernel_launch(void* const* d_in, const int* in_sizes, int n_in,
                              void* d_out, int out_size) {
    const float* x         = (const float*)d_in[0];
    const float* rnoise    = (const float*)d_in[1];
    const float* wq        = (const float*)d_in[2];
    const float* wk        = (const float*)d_in[3];
    const float* wv        = (const float*)d_in[4];
    const float* w_proj    = (const float*)d_in[5];
    const float* b_proj    = (const float*)d_in[6];
    const float* ln1_g     = (const float*)d_in[7];
    const float* ln1_b     = (const float*)d_in[8];
    const float* ln2_g     = (const float*)d_in[9];
    const float* ln2_b     = (const float*)d_in[10];
    const float* w_route   = (const float*)d_in[11];
    const float* b_route   = (const float*)d_in[12];
    const float* w_noise   = (const float*)d_in[13];
    const float* b_noise   = (const float*)d_in[14];
    const float* temp      = (const float*)d_in[15];
    const float* deep_w1   = (const float*)d_in[16];
    const float* deep_b1   = (const float*)d_in[17];
    const float* deep_w2   = (const float*)d_in[18];
    const float* deep_b2   = (const float*)d_in[19];
    const float* deep_w3   = (const float*)d_in[20];
    const float* deep_b3   = (const float*)d_in[21];
    const float* deep_ln_g = (const float*)d_in[22];
    const float* deep_ln_b = (const float*)d_in[23];
    const float* simple_w1   = (const float*)d_in[24];
    const float* simple_b1   = (const float*)d_in[25];
    const float* simple_w2   = (const float*)d_in[26];
    const float* simple_b2   = (const float*)d_in[27];
    const float* simple_ln_g = (const float*)d_in[28];
    const float* simple_ln_b = (const float*)d_in[29];

    float* out = (float*)d_out;

    float *h1, *qkv, *S, *o, *h2, *mid1, *mid2, *Yc, *Wqkv, *gw;
    int *cnt, *tok, *slot;
    cudaGetSymbolAddress((void**)&h1,   g_h1);
    cudaGetSymbolAddress((void**)&qkv,  g_qkv);
    cudaGetSymbolAddress((void**)&S,    g_S);
    cudaGetSymbolAddress((void**)&o,    g_o);
    cudaGetSymbolAddress((void**)&h2,   g_h2);
    cudaGetSymbolAddress((void**)&mid1, g_mid1);
    cudaGetSymbolAddress((void**)&mid2, g_mid2);
    cudaGetSymbolAddress((void**)&Yc,   g_Yc);
    cudaGetSymbolAddress((void**)&Wqkv, g_Wqkv);
    cudaGetSymbolAddress((void**)&cnt,  g_cnt);
    cudaGetSymbolAddress((void**)&tok,  g_tok);
    cudaGetSymbolAddress((void**)&gw,   g_gw);
    cudaGetSymbolAddress((void**)&slot, g_slot);

    // raise dynamic smem limits (idempotent)
    cudaFuncSetAttribute((const void*)tgemm_k<0,false,true,false>, cudaFuncAttributeMaxDynamicSharedMemorySize, TG_SMEM);
    cudaFuncSetAttribute((const void*)tgemm_k<0,true,false,true>,  cudaFuncAttributeMaxDynamicSharedMemorySize, TG_SMEM);
    cudaFuncSetAttribute((const void*)egemm_k<0>, cudaFuncAttributeMaxDynamicSharedMemorySize, TG_SMEM);
    cudaFuncSetAttribute((const void*)egemm_k<1>, cudaFuncAttributeMaxDynamicSharedMemorySize, TG_SMEM);
    cudaFuncSetAttribute((const void*)egemm_k<2>, cudaFuncAttributeMaxDynamicSharedMemorySize, TG_SMEM);
    cudaFuncSetAttribute((const void*)attn_scores_tc, cudaFuncAttributeMaxDynamicSharedMemorySize, SC_SMEM);
    cudaFuncSetAttribute((const void*)attn_pv_tc,     cudaFuncAttributeMaxDynamicSharedMemorySize, PV_SMEM);

    zero_cnt_kernel<<<1, 32>>>(cnt);
    pack_wqkv_kernel<<<(C_ * C3_ + 255) / 256, 256>>>(wq, wk, wv);

    // ln1 -> h1 (rounded) ; qkv = h1 @ Wqkv (Wqkv pre-rounded; rounded out)
    ln_kernel<true><<<N_, 256>>>(x, ln1_g, ln1_b, h1, nullptr);
    tgemm_k<0, false, true, false><<<dim3(C3_ / 128, N_ / 128), 256, TG_SMEM>>>(
        h1, C_, Wqkv, nullptr, nullptr, qkv, C3_, N_, C3_, C_);

    // attention (tensor core)
    attn_scores_tc<<<dim3(T_ / 128, T_ / 128, BH_), 256, SC_SMEM>>>(qkv, S);
    softmax_causal_kernel<<<BH_ * T_, 128>>>(S);
    attn_pv_tc<<<dim3(T_ / 128, BH_), 256, PV_SMEM>>>(qkv, S, o);

    // out = x + o @ w_proj + b_proj   (w_proj rounded in-kernel)
    tgemm_k<0, true, false, true><<<dim3(C_ / 128, N_ / 128), 256, TG_SMEM>>>(
        o, C_, w_proj, b_proj, x, out, C_, N_, C_, C_);

    // ln2 -> h2 (exact) + h2r (rounded, reuses h1) ; router
    ln_kernel<false><<<N_, 256>>>(out, ln2_g, ln2_b, h2, h1);
    router_kernel<<<N_ / 8, 256>>>(h2, w_route, b_route, w_noise, b_noise,
                                   rnoise, temp, cnt, tok, gw, slot);

    // experts, batched across blockIdx.z
    // w1 for all 8 experts: mid1[z] = gelu(h2r @ w1[z] + b1[z])
    egemm_k<0><<<dim3(F_ / 128, N_ / 128, E_), 256, TG_SMEM>>>(
        h1, mid1, mid2, deep_w1, simple_w1, deep_b1, simple_b1, mid1, tok, cnt);
    // deep w2 (z=0,1): mid2[z] = gelu(mid1[z] @ w2[z] + b2[z])
    egemm_k<1><<<dim3(F_ / 128, N_ / 128, 2), 256, TG_SMEM>>>(
        h1, mid1, mid2, deep_w2, nullptr, deep_b2, nullptr, mid2, tok, cnt);
    // final layer all 8: Yc[z] = (deep? mid2@w3 : mid1@w2) + bias
    egemm_k<2><<<dim3(C_ / 128, N_ / 128, E_), 256, TG_SMEM>>>(
        h1, mid1, mid2, deep_w3, simple_w2, deep_b3, simple_b2, Yc, tok, cnt);
    // batched epilogue: Yc[z][m] = gate * LN(h2 + Yc[z][m])
    expert_epi_batched<<<dim3(N_, E_), 256>>>(Yc, h2, tok, gw, cnt,
                                              deep_ln_g, deep_ln_b,
                                              simple_ln_g, simple_ln_b);
    // final combine
    combine_kernel<<<N_, 256>>>(Yc, slot, out);
}

// round 15
// speedup vs baseline: 1.5414x; 1.0618x over previous
#include <cuda_runtime.h>
#include <math.h>

// ---------------- problem constants ----------------
#define B_   8
#define T_   1024
#define C_   768
#define H_   12
#define HS_  64
#define E_   8
#define F_   3072
#define N_   (B_*T_)     // 8192 tokens
#define BH_  (B_*H_)     // 96
#define C3_  (3*C_)      // 2304

// dynamic smem sizes
#define TG_SMEM  ((6*128*20 + 6*16*136)*4)   // 113664 (6-stage ring)
#define SC_SMEM  ((128*68 + 64*136)*4)       // 69632
#define PV_SMEM  ((6*128*20 + 6*16*72)*4)    // 89088

// ---------------- scratch (device globals; no allocation) ----------------
__device__ float g_h1  [N_*C_];               // h1 (rounded), later h2r (rounded)
__device__ float g_qkv [N_*C3_];
__device__ float g_S   [(size_t)BH_*T_*T_];
__device__ float g_o   [N_*C_];
__device__ float g_h2  [N_*C_];               // exact h2
__device__ float g_mid1[(size_t)E_*N_*F_];    // per-expert slabs
__device__ float g_mid2[(size_t)2*N_*F_];     // deep mid2 slabs
__device__ float g_Yc  [(size_t)E_*N_*C_];    // per-slot expert outputs
__device__ float g_Wqkv[C_*C3_];
__device__ int   g_cnt [E_];
__device__ int   g_tok [E_*N_];
__device__ float g_gw  [E_*N_];
__device__ int   g_slot[2*N_];

// ---------------- helpers ----------------
__device__ __forceinline__ float gelu_f(float z) {
    return 0.5f * z * (1.0f + erff(z * 0.70710678118654752440f));
}

__device__ __forceinline__ float rna_tf32(float f) {
    unsigned r;
    asm("cvt.rna.tf32.f32 %0, %1;" : "=r"(r) : "f"(f));
    return __uint_as_float(r);
}

__device__ __forceinline__ void cpa16(void* smem_dst, const void* gsrc) {
    unsigned d = (unsigned)__cvta_generic_to_shared(smem_dst);
    asm volatile("cp.async.cg.shared.global [%0], [%1], 16;" :: "r"(d), "l"(gsrc));
}

__device__ __forceinline__ void ldsm4(unsigned &r0, unsigned &r1, unsigned &r2, unsigned &r3,
                                      const void* p) {
    unsigned addr = (unsigned)__cvta_generic_to_shared(p);
    asm volatile("ldmatrix.sync.aligned.m8n8.x4.shared.b16 {%0,%1,%2,%3}, [%4];"
        : "=r"(r0), "=r"(r1), "=r"(r2), "=r"(r3) : "r"(addr));
}

__device__ __forceinline__ void mma_tf32(float* c, const unsigned* a, const unsigned* b) {
    asm volatile("mma.sync.aligned.m16n8k8.row.col.f32.tf32.tf32.f32 "
        "{%0,%1,%2,%3}, {%4,%5,%6,%7}, {%8,%9}, {%0,%1,%2,%3};"
        : "+f"(c[0]), "+f"(c[1]), "+f"(c[2]), "+f"(c[3])
        : "r"(a[0]), "r"(a[1]), "r"(a[2]), "r"(a[3]), "r"(b[0]), "r"(b[1]));
}

__device__ __forceinline__ float blockReduceSum256(float v) {
    __shared__ float sh[8];
    int lane = threadIdx.x & 31, w = threadIdx.x >> 5;
    #pragma unroll
    for (int o = 16; o; o >>= 1) v += __shfl_down_sync(0xffffffffu, v, o);
    if (lane == 0) sh[w] = v;
    __syncthreads();
    float r;
    if (w == 0) {
        float t = (lane < 8) ? sh[lane] : 0.f;
        #pragma unroll
        for (int o = 4; o; o >>= 1) t += __shfl_down_sync(0xffffffffu, t, o);
        if (lane == 0) sh[0] = t;
    }
    __syncthreads();
    r = sh[0];
    __syncthreads();
    return r;
}

// ---------------- small setup kernels ----------------
__global__ void zero_cnt_kernel(int* cnt) {
    if (threadIdx.x < E_) cnt[threadIdx.x] = 0;
}

// pack wq,wk,wv (H,C,HS) -> Wqkv[C][3C], rounded
__global__ void pack_wqkv_kernel(const float* __restrict__ wq,
                                 const float* __restrict__ wk,
                                 const float* __restrict__ wv) {
    int idx = blockIdx.x * 256 + threadIdx.x;
    if (idx >= C_ * C3_) return;
    int c   = idx / C3_;
    int col = idx - c * C3_;
    int which = col / C_;
    int rem   = col - which * C_;
    int h = rem / HS_;
    int d = rem - h * HS_;
    const float* w = (which == 0) ? wq : ((which == 1) ? wk : wv);
    g_Wqkv[idx] = rna_tf32(w[(h * C_ + c) * HS_ + d]);
}

// LayerNorm; ROUND_MAIN rounds main output; outR (optional) gets rounded copy
template<bool ROUND_MAIN>
__global__ __launch_bounds__(256) void ln_kernel(const float* __restrict__ in,
                                                 const float* __restrict__ g,
                                                 const float* __restrict__ b,
                                                 float* __restrict__ out,
                                                 float* __restrict__ outR) {
    int row = blockIdx.x;
    const float* p = in + (size_t)row * C_;
    int t = threadIdx.x;
    float x0 = p[t], x1 = p[t + 256], x2 = p[t + 512];
    float mean = blockReduceSum256(x0 + x1 + x2) * (1.0f / C_);
    float d0 = x0 - mean, d1 = x1 - mean, d2 = x2 - mean;
    float var = blockReduceSum256(d0*d0 + d1*d1 + d2*d2) * (1.0f / C_);
    float rstd = rsqrtf(var + 1e-5f);
    float v0 = d0 * rstd * g[t]       + b[t];
    float v1 = d1 * rstd * g[t + 256] + b[t + 256];
    float v2 = d2 * rstd * g[t + 512] + b[t + 512];
    float* o = out + (size_t)row * C_;
    if (ROUND_MAIN) {
        o[t] = rna_tf32(v0); o[t+256] = rna_tf32(v1); o[t+512] = rna_tf32(v2);
    } else {
        o[t] = v0; o[t+256] = v1; o[t+512] = v2;
    }
    if (outR) {
        float* r = outR + (size_t)row * C_;
        r[t] = rna_tf32(v0); r[t+256] = rna_tf32(v1); r[t+512] = rna_tf32(v2);
    }
}

// ---------------- shared tf32 GEMM body (6-stage ring, 2 tiles/barrier) ----------------
// Block 128x128x16, 8 warps 2x4, warp tile 64x32. Nn%128==0, Kk%32==0 (even tiles).
// RB: round B elements (raw fp32 weights) to tf32 at fragment load.
template<bool GATHER, int ACT, bool RESID, bool ROUND, bool RB>
__device__ __forceinline__ void gemm_body(
    const float* __restrict__ A, int lda,
    const float* __restrict__ Bm,
    const float* __restrict__ bias,
    const float* __restrict__ resid,
    float* __restrict__ Cm, int ldc,
    int M, int Nn, int Kk,
    const int* __restrict__ rows,
    int m0, int n0)
{
    extern __shared__ float sm[];
    float* sA = sm;                 // [6][128][20]
    float* sB = sm + 6*128*20;      // [6][16][136]
    __shared__ int rIdx[128];

    int tid = threadIdx.x;
    if (GATHER) {
        if (tid < 128) { int m = m0 + tid; rIdx[tid] = rows[(m < M) ? m : (M - 1)]; }
        __syncthreads();
    }

    int aRow = tid & 127;
    int aCol = (tid >> 7) * 4;       // {0,4}; second load at +8
    int aSrcRow;
    if (GATHER) aSrcRow = rIdx[aRow];
    else { int gm = m0 + aRow; aSrcRow = (gm < M) ? gm : (M - 1); }
    const float* aPtr = A + (size_t)aSrcRow * lda;
    int bK = tid >> 4;
    int bN = (tid & 15) * 4;
    const float* bPtr = Bm + (size_t)bK * Nn + n0;

    int nTiles = Kk / 16;   // even, >= 4

    // prologue: stages 0..3
    #pragma unroll
    for (int s = 0; s < 4; s++) {
        int k0 = s * 16;
        cpa16(&sA[((s*128) + aRow)*20 + aCol],     aPtr + k0 + aCol);
        cpa16(&sA[((s*128) + aRow)*20 + aCol + 8], aPtr + k0 + aCol + 8);
        const float* bp = bPtr + (size_t)k0 * Nn;
        cpa16(&sB[((s*16) + bK)*136 + bN],      bp + bN);
        cpa16(&sB[((s*16) + bK)*136 + bN + 64], bp + bN + 64);
        asm volatile("cp.async.commit_group;");
    }

    int wid = tid >> 5, lane = tid & 31;
    int warpM = (wid >> 2) * 64;
    int warpN = (wid & 3) * 32;
    int g  = lane >> 2;
    int tg = lane & 3;
    int aRowIn = ((lane >> 3) & 1) * 8 + (lane & 7);
    int aColIn = ((lane >> 3) >> 1) * 4;

    float acc[4][4][4];
    #pragma unroll
    for (int i = 0; i < 4; i++)
        #pragma unroll
        for (int j = 0; j < 4; j++)
            #pragma unroll
            for (int r = 0; r < 4; r++) acc[i][j][r] = 0.f;

    for (int t = 0; t < nTiles; t += 2) {
        // tiles t, t+1 ready when <=2 groups outstanding
        asm volatile("cp.async.wait_group 2;");
        __syncthreads();

        // prefetch tiles t+4, t+5 (their buffers held tiles t-2, t-1: consumed
        // before the barrier we just passed)
        #pragma unroll
        for (int u = 4; u < 6; u++) {
            int tn = t + u;
            if (tn < nTiles) {
                int stg = tn % 6;
                int k0 = tn * 16;
                cpa16(&sA[((stg*128) + aRow)*20 + aCol],     aPtr + k0 + aCol);
                cpa16(&sA[((stg*128) + aRow)*20 + aCol + 8], aPtr + k0 + aCol + 8);
                const float* bp = bPtr + (size_t)k0 * Nn;
                cpa16(&sB[((stg*16) + bK)*136 + bN],      bp + bN);
                cpa16(&sB[((stg*16) + bK)*136 + bN + 64], bp + bN + 64);
            }
            asm volatile("cp.async.commit_group;");
        }

        // compute tiles t and t+1 (64 HMMA/warp between barriers)
        #pragma unroll
        for (int u = 0; u < 2; u++) {
            int buf = (t + u) % 6;
            const float* Ab = sA + buf*128*20;
            const float* Bb = sB + buf*16*136;
            #pragma unroll
            for (int s = 0; s < 2; s++) {
                unsigned af[4][4];
                #pragma unroll
                for (int i = 0; i < 4; i++)
                    ldsm4(af[i][0], af[i][1], af[i][2], af[i][3],
                          &Ab[(warpM + i*16 + aRowIn)*20 + s*8 + aColIn]);
                unsigned bf[4][2];
                #pragma unroll
                for (int j = 0; j < 4; j++) {
                    int col = warpN + j*8 + g;
                    float b0 = Bb[(s*8 + tg)*136 + col];
                    float b1 = Bb[(s*8 + tg + 4)*136 + col];
                    if (RB) { b0 = rna_tf32(b0); b1 = rna_tf32(b1); }
                    bf[j][0] = __float_as_uint(b0);
                    bf[j][1] = __float_as_uint(b1);
                }
                #pragma unroll
                for (int i = 0; i < 4; i++)
                    #pragma unroll
                    for (int j = 0; j < 4; j++)
                        mma_tf32(acc[i][j], af[i], bf[j]);
            }
        }
    }

    #pragma unroll
    for (int i = 0; i < 4; i++) {
        int r0 = m0 + warpM + i * 16 + g;
        int r1 = r0 + 8;
        #pragma unroll
        for (int j = 0; j < 4; j++) {
            int col = n0 + warpN + j * 8 + tg * 2;
            float b0 = 0.f, b1 = 0.f;
            if (bias) { b0 = bias[col]; b1 = bias[col + 1]; }
            if (r0 < M) {
                float v0 = acc[i][j][0] + b0;
                float v1 = acc[i][j][1] + b1;
                if (ACT == 1) { v0 = gelu_f(v0); v1 = gelu_f(v1); }
                if (RESID) {
                    v0 += resid[(size_t)r0 * ldc + col];
                    v1 += resid[(size_t)r0 * ldc + col + 1];
                }
                if (ROUND) { v0 = rna_tf32(v0); v1 = rna_tf32(v1); }
                *(float2*)&Cm[(size_t)r0 * ldc + col] = make_float2(v0, v1);
            }
            if (r1 < M) {
                float v2 = acc[i][j][2] + b0;
                float v3 = acc[i][j][3] + b1;
                if (ACT == 1) { v2 = gelu_f(v2); v3 = gelu_f(v3); }
                if (RESID) {
                    v2 += resid[(size_t)r1 * ldc + col];
                    v3 += resid[(size_t)r1 * ldc + col + 1];
                }
                if (ROUND) { v2 = rna_tf32(v2); v3 = rna_tf32(v3); }
                *(float2*)&Cm[(size_t)r1 * ldc + col] = make_float2(v2, v3);
            }
        }
    }
}

// plain GEMM wrapper (QKV, proj)
template<int ACT, bool RESID, bool ROUND, bool RB>
__global__ __launch_bounds__(256) void tgemm_k(
    const float* __restrict__ A, int lda,
    const float* __restrict__ Bm,
    const float* __restrict__ bias,
    const float* __restrict__ resid,
    float* __restrict__ Cm, int ldc,
    int M, int Nn, int Kk)
{
    int m0 = blockIdx.y * 128;
    if (m0 >= M) return;
    gemm_body<false, ACT, RESID, ROUND, RB>(A, lda, Bm, bias, resid, Cm, ldc,
                                            M, Nn, Kk, nullptr, m0, blockIdx.x * 128);
}

// ---------------- batched expert GEMMs (blockIdx.z = expert) ----------------
template<int MODE>
__global__ __launch_bounds__(256) void egemm_k(
    const float* __restrict__ hA,
    const float* __restrict__ mid1,
    const float* __restrict__ mid2,
    const float* __restrict__ dW, const float* __restrict__ sW,
    const float* __restrict__ dBias, const float* __restrict__ sBias,
    float* __restrict__ Cout,
    const int* __restrict__ tok, const int* __restrict__ cnt)
{
    int z = blockIdx.z;
    int M = cnt[z];
    int m0 = blockIdx.y * 128;
    if (m0 >= M) return;
    int n0 = blockIdx.x * 128;
    bool deep = (MODE == 1) ? true : (z < 2);

    if (MODE == 0) {
        const float* W  = deep ? dW + (size_t)z * C_ * F_ : sW + (size_t)(z - 2) * C_ * F_;
        const float* bs = deep ? dBias + (size_t)z * F_   : sBias + (size_t)(z - 2) * F_;
        float* Cm = Cout + (size_t)z * N_ * F_;
        gemm_body<true, 1, false, true, true>(hA, C_, W, bs, nullptr, Cm, F_,
                                              M, F_, C_, tok + (size_t)z * N_, m0, n0);
    } else if (MODE == 1) {
        const float* A  = mid1 + (size_t)z * N_ * F_;
        const float* W  = dW + (size_t)z * F_ * F_;
        const float* bs = dBias + (size_t)z * F_;
        float* Cm = Cout + (size_t)z * N_ * F_;
        gemm_body<false, 1, false, true, true>(A, F_, W, bs, nullptr, Cm, F_,
                                               M, F_, F_, nullptr, m0, n0);
    } else {
        const float* A  = deep ? mid2 + (size_t)z * N_ * F_ : mid1 + (size_t)z * N_ * F_;
        const float* W  = deep ? dW + (size_t)z * F_ * C_   : sW + (size_t)(z - 2) * F_ * C_;
        const float* bs = deep ? dBias + (size_t)z * C_     : sBias + (size_t)(z - 2) * C_;
        float* Cm = Cout + (size_t)z * N_ * C_;
        gemm_body<false, 0, false, false, true>(A, F_, W, bs, nullptr, Cm, C_,
                                                M, C_, F_, nullptr, m0, n0);
    }
}

// ---------------- attention scores (tf32 mma, single-shot K=64) ----------------
__global__ __launch_bounds__(256) void attn_scores_tc(const float* __restrict__ qkv,
                                                      float* __restrict__ S) {
    int t0 = blockIdx.y * 128, s0 = blockIdx.x * 128;
    if (s0 > t0) return;
    int bh = blockIdx.z;
    int b = bh / H_, h = bh - b * H_;

    extern __shared__ float sm[];
    float* Qs = sm;              // [128][68]
    float* Ks = sm + 128*68;     // [64][136]  ([d][s])
    int tid = threadIdx.x;

    const float* qbase = qkv + (size_t)(b * T_ + t0) * C3_ + h * HS_;
    #pragma unroll
    for (int l = 0; l < 8; l++) {
        int idx = tid + l * 256;
        int r = idx >> 4, q = idx & 15;
        cpa16(&Qs[r*68 + q*4], qbase + (size_t)r * C3_ + q * 4);
    }
    asm volatile("cp.async.commit_group;");

    const float* kbase = qkv + (size_t)(b * T_ + s0) * C3_ + C_ + h * HS_;
    #pragma unroll
    for (int l = 0; l < 8; l++) {
        int idx = tid + l * 256;
        int s = idx & 127, q = idx >> 7;
        float4 v = *(const float4*)(kbase + (size_t)s * C3_ + q * 4);
        Ks[(q*4+0)*136 + s] = v.x;
        Ks[(q*4+1)*136 + s] = v.y;
        Ks[(q*4+2)*136 + s] = v.z;
        Ks[(q*4+3)*136 + s] = v.w;
    }
    asm volatile("cp.async.wait_group 0;");
    __syncthreads();

    int wid = tid >> 5, lane = tid & 31;
    int warpM = (wid >> 2) * 64, warpN = (wid & 3) * 32;
    int g = lane >> 2, tg = lane & 3;
    int aRowIn = ((lane >> 3) & 1) * 8 + (lane & 7);
    int aColIn = ((lane >> 3) >> 1) * 4;

    float acc[4][4][4];
    #pragma unroll
    for (int i = 0; i < 4; i++)
        #pragma unroll
        for (int j = 0; j < 4; j++)
            #pragma unroll
            for (int r = 0; r < 4; r++) acc[i][j][r] = 0.f;

    #pragma unroll
    for (int ks = 0; ks < 8; ks++) {
        unsigned af[4][4];
        #pragma unroll
        for (int i = 0; i < 4; i++)
            ldsm4(af[i][0], af[i][1], af[i][2], af[i][3],
                  &Qs[(warpM + i*16 + aRowIn)*68 + ks*8 + aColIn]);
        unsigned bf[4][2];
        #pragma unroll
        for (int j = 0; j < 4; j++) {
            int col = warpN + j*8 + g;
            bf[j][0] = __float_as_uint(Ks[(ks*8 + tg)*136 + col]);
            bf[j][1] = __float_as_uint(Ks[(ks*8 + tg + 4)*136 + col]);
        }
        #pragma unroll
        for (int i = 0; i < 4; i++)
            #pragma unroll
            for (int j = 0; j < 4; j++)
                mma_tf32(acc[i][j], af[i], bf[j]);
    }

    const float scale = 0.03608439182435161f;   // 768^-0.5
    float* op = S + ((size_t)bh * T_ + t0) * T_ + s0;
    #pragma unroll
    for (int i = 0; i < 4; i++) {
        int r0 = warpM + i * 16 + g;
        int r1 = r0 + 8;
        #pragma unroll
        for (int j = 0; j < 4; j++) {
            int col = warpN + j * 8 + tg * 2;
            *(float2*)&op[(size_t)r0 * T_ + col] =
                make_float2(acc[i][j][0] * scale, acc[i][j][1] * scale);
            *(float2*)&op[(size_t)r1 * T_ + col] =
                make_float2(acc[i][j][2] * scale, acc[i][j][3] * scale);
        }
    }
}

// ---------------- causal softmax (in place, rounds P, zero-fill to tile edge) ----------------
__global__ __launch_bounds__(128) void softmax_causal_kernel(float* __restrict__ S) {
    int row = blockIdx.x;
    int t = row & (T_ - 1);
    float* p = S + (size_t)row * T_;
    int len = t + 1;
    int end = ((t >> 7) + 1) << 7;   // end of diagonal 128-tile
    int tid = threadIdx.x;
    __shared__ float sh[4];

    float mx = -1e30f;
    for (int s = tid; s < len; s += 128) mx = fmaxf(mx, p[s]);
    #pragma unroll
    for (int o = 16; o; o >>= 1) mx = fmaxf(mx, __shfl_down_sync(0xffffffffu, mx, o));
    if ((tid & 31) == 0) sh[tid >> 5] = mx;
    __syncthreads();
    mx = fmaxf(fmaxf(sh[0], sh[1]), fmaxf(sh[2], sh[3]));
    __syncthreads();

    float sum = 0.f;
    for (int s = tid; s < len; s += 128) { float e = __expf(p[s] - mx); p[s] = e; sum += e; }
    #pragma unroll
    for (int o = 16; o; o >>= 1) sum += __shfl_down_sync(0xffffffffu, sum, o);
    if ((tid & 31) == 0) sh[tid >> 5] = sum;
    __syncthreads();
    sum = sh[0] + sh[1] + sh[2] + sh[3];
    float inv = 1.f / sum;
    for (int s = tid; s < len; s += 128) p[s] = rna_tf32(p[s] * inv);
    for (int s = len + tid; s < end; s += 128) p[s] = 0.f;
}

// ---------------- PV (tf32 mma, 6-stage ring, 2 tiles/barrier) ----------------
__global__ __launch_bounds__(256) void attn_pv_tc(const float* __restrict__ qkv,
                                                  const float* __restrict__ P,
                                                  float* __restrict__ O) {
    int t0 = blockIdx.x * 128;
    int bh = blockIdx.y;
    int b = bh / H_, h = bh - b * H_;

    extern __shared__ float sm[];
    float* sA = sm;                 // [6][128][20]
    float* sB = sm + 6*128*20;      // [6][16][72]

    int tid = threadIdx.x;
    const float* aPtr = P + ((size_t)bh * T_ + t0) * T_;
    const float* vbase = qkv + (size_t)(b * T_) * C3_ + 2 * C_ + h * HS_;

    int aRow = tid & 127;
    int aColQ = (tid >> 7) * 8;
    int bK = tid >> 4;
    int bN = (tid & 15) * 4;

    int nTiles = (t0 + 128) / 16;   // even, >= 8

    #pragma unroll
    for (int s = 0; s < 4; s++) {
        int k0 = s * 16;
        cpa16(&sA[((s*128) + aRow)*20 + aColQ],     aPtr + (size_t)aRow * T_ + k0 + aColQ);
        cpa16(&sA[((s*128) + aRow)*20 + aColQ + 4], aPtr + (size_t)aRow * T_ + k0 + aColQ + 4);
        cpa16(&sB[((s*16) + bK)*72 + bN], vbase + (size_t)(k0 + bK) * C3_ + bN);
        asm volatile("cp.async.commit_group;");
    }

    int wid = tid >> 5, lane = tid & 31;
    int warpM = (wid >> 1) * 32;
    int warpN = (wid & 1) * 32;
    int g = lane >> 2, tg = lane & 3;
    int aRowIn = ((lane >> 3) & 1) * 8 + (lane & 7);
    int aColIn = ((lane >> 3) >> 1) * 4;

    float acc[2][4][4];
    #pragma unroll
    for (int i = 0; i < 2; i++)
        #pragma unroll
        for (int j = 0; j < 4; j++)
            #pragma unroll
            for (int r = 0; r < 4; r++) acc[i][j][r] = 0.f;

    for (int t = 0; t < nTiles; t += 2) {
        asm volatile("cp.async.wait_group 2;");
        __syncthreads();

        #pragma unroll
        for (int u = 4; u < 6; u++) {
            int tn = t + u;
            if (tn < nTiles) {
                int stg = tn % 6;
                int k0 = tn * 16;
                cpa16(&sA[((stg*128) + aRow)*20 + aColQ],     aPtr + (size_t)aRow * T_ + k0 + aColQ);
                cpa16(&sA[((stg*128) + aRow)*20 + aColQ + 4], aPtr + (size_t)aRow * T_ + k0 + aColQ + 4);
                cpa16(&sB[((stg*16) + bK)*72 + bN], vbase + (size_t)(k0 + bK) * C3_ + bN);
            }
            asm volatile("cp.async.commit_group;");
        }

        #pragma unroll
        for (int u = 0; u < 2; u++) {
            int buf = (t + u) % 6;
            const float* Ab = sA + buf*128*20;
            const float* Bb = sB + buf*16*72;
            #pragma unroll
            for (int s = 0; s < 2; s++) {
                unsigned af[2][4];
                #pragma unroll
                for (int i = 0; i < 2; i++)
                    ldsm4(af[i][0], af[i][1], af[i][2], af[i][3],
                          &Ab[(warpM + i*16 + aRowIn)*20 + s*8 + aColIn]);
                unsigned bf[4][2];
                #pragma unroll
                for (int j = 0; j < 4; j++) {
                    int col = warpN + j*8 + g;
                    bf[j][0] = __float_as_uint(Bb[(s*8 + tg)*72 + col]);
                    bf[j][1] = __float_as_uint(Bb[(s*8 + tg + 4)*72 + col]);
                }
                #pragma unroll
                for (int i = 0; i < 2; i++)
                    #pragma unroll
                    for (int j = 0; j < 4; j++)
                        mma_tf32(acc[i][j], af[i], bf[j]);
            }
        }
    }

    #pragma unroll
    for (int i = 0; i < 2; i++) {
        int r0 = warpM + i * 16 + g;
        int r1 = r0 + 8;
        #pragma unroll
        for (int j = 0; j < 4; j++) {
            int col = h * HS_ + warpN + j * 8 + tg * 2;
            *(float2*)&O[(size_t)(b * T_ + t0 + r0) * C_ + col] =
                make_float2(rna_tf32(acc[i][j][0]), rna_tf32(acc[i][j][1]));
            *(float2*)&O[(size_t)(b * T_ + t0 + r1) * C_ + col] =
                make_float2(rna_tf32(acc[i][j][2]), rna_tf32(acc[i][j][3]));
        }
    }
}

// ---------------- router: noisy top-2 + assignment + slot table ----------------
__global__ __launch_bounds__(256) void router_kernel(
    const float* __restrict__ h2,
    const float* __restrict__ wr, const float* __restrict__ br,
    const float* __restrict__ wn, const float* __restrict__ bn,
    const float* __restrict__ noise, const float* __restrict__ temp_p,
    int* __restrict__ cnt, int* __restrict__ tok, float* __restrict__ gw,
    int* __restrict__ slot)
{
    int n = blockIdx.x * 8 + (threadIdx.x >> 5);
    if (n >= N_) return;
    int lane = threadIdx.x & 31;
    float ar[E_] = {}, an[E_] = {};
    const float* hp = h2 + (size_t)n * C_;
    for (int c = lane; c < C_; c += 32) {
        float hv = hp[c];
        const float* wrp = wr + c * E_;
        const float* wnp = wn + c * E_;
        #pragma unroll
        for (int e = 0; e < E_; e++) {
            ar[e] = fmaf(hv, wrp[e], ar[e]);
            an[e] = fmaf(hv, wnp[e], an[e]);
        }
    }
    #pragma unroll
    for (int e = 0; e < E_; e++) {
        #pragma unroll
        for (int o = 16; o; o >>= 1) {
            ar[e] += __shfl_down_sync(0xffffffffu, ar[e], o);
            an[e] += __shfl_down_sync(0xffffffffu, an[e], o);
        }
    }
    if (lane == 0) {
        float t = fminf(fmaxf(*temp_p, 0.5f), 2.0f);
        float noisy[E_];
        #pragma unroll
        for (int e = 0; e < E_; e++) {
            float logit = ar[e] + br[e];
            float z = an[e] + bn[e];
            float sp = fmaxf(z, 0.f) + log1pf(expf(-fabsf(z)));
            noisy[e] = logit + t * noise[(size_t)n * E_ + e] * sp;
        }
        int i1 = 0;
        #pragma unroll
        for (int e = 1; e < E_; e++) if (noisy[e] > noisy[i1]) i1 = e;
        int i2 = -1;
        #pragma unroll
        for (int e = 0; e < E_; e++)
            if (e != i1 && (i2 < 0 || noisy[e] > noisy[i2])) i2 = e;
        float m = fmaxf(noisy[i1], noisy[i2]);
        float e1 = __expf(noisy[i1] - m), e2 = __expf(noisy[i2] - m);
        float inv = 1.f / (e1 + e2);
        int p1 = atomicAdd(&cnt[i1], 1); tok[i1 * N_ + p1] = n; gw[i1 * N_ + p1] = e1 * inv;
        int p2 = atomicAdd(&cnt[i2], 1); tok[i2 * N_ + p2] = n; gw[i2 * N_ + p2] = e2 * inv;
        slot[2 * n]     = i1 * N_ + p1;
        slot[2 * n + 1] = i2 * N_ + p2;
    }
}

// ---------------- slot epilogue: Yc[s] = gate * LN(h2[n] + Yc[s]), grid = 2N slots ----------------
__global__ __launch_bounds__(256) void expert_epi_slots(
    float* __restrict__ Yc, const float* __restrict__ h2,
    const int* __restrict__ tok, const float* __restrict__ gw,
    const int* __restrict__ slot,
    const float* __restrict__ dlg, const float* __restrict__ dlb,
    const float* __restrict__ slg, const float* __restrict__ slb)
{
    int s = slot[blockIdx.x];
    int z = s >> 13;            // /N_ (8192)
    bool deep = z < 2;
    const float* lg = deep ? dlg + (size_t)z * C_ : slg + (size_t)(z - 2) * C_;
    const float* lb = deep ? dlb + (size_t)z * C_ : slb + (size_t)(z - 2) * C_;
    int n = tok[s];
    float g = gw[s];
    float* yp = Yc + (size_t)s * C_;
    const float* hp = h2 + (size_t)n * C_;
    int t = threadIdx.x;
    float z0 = hp[t]       + yp[t];
    float z1 = hp[t + 256] + yp[t + 256];
    float z2 = hp[t + 512] + yp[t + 512];
    float mean = blockReduceSum256(z0 + z1 + z2) * (1.0f / C_);
    float d0 = z0 - mean, d1 = z1 - mean, d2 = z2 - mean;
    float var = blockReduceSum256(d0*d0 + d1*d1 + d2*d2) * (1.0f / C_);
    float rstd = rsqrtf(var + 1e-5f);
    yp[t]       = g * (d0 * rstd * lg[t]       + lb[t]);
    yp[t + 256] = g * (d1 * rstd * lg[t + 256] + lb[t + 256]);
    yp[t + 512] = g * (d2 * rstd * lg[t + 512] + lb[t + 512]);
}

// ---------------- final combine: out[n] += Yc[slot0] + Yc[slot1] ----------------
__global__ __launch_bounds__(256) void combine_kernel(
    const float* __restrict__ Yc, const int* __restrict__ slot,
    float* __restrict__ out)
{
    int n = blockIdx.x;
    const float* a = Yc + (size_t)slot[2 * n] * C_;
    const float* b = Yc + (size_t)slot[2 * n + 1] * C_;
    float* op = out + (size_t)n * C_;
    int t = threadIdx.x;
    op[t]       += a[t]       + b[t];
    op[t + 256] += a[t + 256] + b[t + 256];
    op[t + 512] += a[t + 512] + b[t + 512];
}

// ---------------- launch ----------------
extern "C" void kernel_launch(void* const* d_in, const int* in_sizes, int n_in,
                              void* d_out, int out_size) {
    const float* x         = (const float*)d_in[0];
    const float* rnoise    = (const float*)d_in[1];
    const float* wq        = (const float*)d_in[2];
    const float* wk        = (const float*)d_in[3];
    const float* wv        = (const float*)d_in[4];
    const float* w_proj    = (const float*)d_in[5];
    const float* b_proj    = (const float*)d_in[6];
    const float* ln1_g     = (const float*)d_in[7];
    const float* ln1_b     = (const float*)d_in[8];
    const float* ln2_g     = (const float*)d_in[9];
    const float* ln2_b     = (const float*)d_in[10];
    const float* w_route   = (const float*)d_in[11];
    const float* b_route   = (const float*)d_in[12];
    const float* w_noise   = (const float*)d_in[13];
    const float* b_noise   = (const float*)d_in[14];
    const float* temp      = (const float*)d_in[15];
    const float* deep_w1   = (const float*)d_in[16];
    const float* deep_b1   = (const float*)d_in[17];
    const float* deep_w2   = (const float*)d_in[18];
    const float* deep_b2   = (const float*)d_in[19];
    const float* deep_w3   = (const float*)d_in[20];
    const float* deep_b3   = (const float*)d_in[21];
    const float* deep_ln_g = (const float*)d_in[22];
    const float* deep_ln_b = (const float*)d_in[23];
    const float* simple_w1   = (const float*)d_in[24];
    const float* simple_b1   = (const float*)d_in[25];
    const float* simple_w2   = (const float*)d_in[26];
    const float* simple_b2   = (const float*)d_in[27];
    const float* simple_ln_g = (const float*)d_in[28];
    const float* simple_ln_b = (const float*)d_in[29];

    float* out = (float*)d_out;

    float *h1, *qkv, *S, *o, *h2, *mid1, *mid2, *Yc, *Wqkv, *gw;
    int *cnt, *tok, *slot;
    cudaGetSymbolAddress((void**)&h1,   g_h1);
    cudaGetSymbolAddress((void**)&qkv,  g_qkv);
    cudaGetSymbolAddress((void**)&S,    g_S);
    cudaGetSymbolAddress((void**)&o,    g_o);
    cudaGetSymbolAddress((void**)&h2,   g_h2);
    cudaGetSymbolAddress((void**)&mid1, g_mid1);
    cudaGetSymbolAddress((void**)&mid2, g_mid2);
    cudaGetSymbolAddress((void**)&Yc,   g_Yc);
    cudaGetSymbolAddress((void**)&Wqkv, g_Wqkv);
    cudaGetSymbolAddress((void**)&cnt,  g_cnt);
    cudaGetSymbolAddress((void**)&tok,  g_tok);
    cudaGetSymbolAddress((void**)&gw,   g_gw);
    cudaGetSymbolAddress((void**)&slot, g_slot);

    // raise dynamic smem limits (idempotent)
    cudaFuncSetAttribute((const void*)tgemm_k<0,false,true,false>, cudaFuncAttributeMaxDynamicSharedMemorySize, TG_SMEM);
    cudaFuncSetAttribute((const void*)tgemm_k<0,true,false,true>,  cudaFuncAttributeMaxDynamicSharedMemorySize, TG_SMEM);
    cudaFuncSetAttribute((const void*)egemm_k<0>, cudaFuncAttributeMaxDynamicSharedMemorySize, TG_SMEM);
    cudaFuncSetAttribute((const void*)egemm_k<1>, cudaFuncAttributeMaxDynamicSharedMemorySize, TG_SMEM);
    cudaFuncSetAttribute((const void*)egemm_k<2>, cudaFuncAttributeMaxDynamicSharedMemorySize, TG_SMEM);
    cudaFuncSetAttribute((const void*)attn_scores_tc, cudaFuncAttributeMaxDynamicSharedMemorySize, SC_SMEM);
    cudaFuncSetAttribute((const void*)attn_pv_tc,     cudaFuncAttributeMaxDynamicSharedMemorySize, PV_SMEM);

    zero_cnt_kernel<<<1, 32>>>(cnt);
    pack_wqkv_kernel<<<(C_ * C3_ + 255) / 256, 256>>>(wq, wk, wv);

    // ln1 -> h1 (rounded) ; qkv = h1 @ Wqkv (Wqkv pre-rounded; rounded out)
    ln_kernel<true><<<N_, 256>>>(x, ln1_g, ln1_b, h1, nullptr);
    tgemm_k<0, false, true, false><<<dim3(C3_ / 128, N_ / 128), 256, TG_SMEM>>>(
        h1, C_, Wqkv, nullptr, nullptr, qkv, C3_, N_, C3_, C_);

    // attention (tensor core)
    attn_scores_tc<<<dim3(T_ / 128, T_ / 128, BH_), 256, SC_SMEM>>>(qkv, S);
    softmax_causal_kernel<<<BH_ * T_, 128>>>(S);
    attn_pv_tc<<<dim3(T_ / 128, BH_), 256, PV_SMEM>>>(qkv, S, o);

    // out = x + o @ w_proj + b_proj   (w_proj rounded in-kernel)
    tgemm_k<0, true, false, true><<<dim3(C_ / 128, N_ / 128), 256, TG_SMEM>>>(
        o, C_, w_proj, b_proj, x, out, C_, N_, C_, C_);

    // ln2 -> h2 (exact) + h2r (rounded, reuses h1) ; router
    ln_kernel<false><<<N_, 256>>>(out, ln2_g, ln2_b, h2, h1);
    router_kernel<<<N_ / 8, 256>>>(h2, w_route, b_route, w_noise, b_noise,
                                   rnoise, temp, cnt, tok, gw, slot);

    // experts, batched across blockIdx.z
    egemm_k<0><<<dim3(F_ / 128, N_ / 128, E_), 256, TG_SMEM>>>(
        h1, mid1, mid2, deep_w1, simple_w1, deep_b1, simple_b1, mid1, tok, cnt);
    egemm_k<1><<<dim3(F_ / 128, N_ / 128, 2), 256, TG_SMEM>>>(
        h1, mid1, mid2, deep_w2, nullptr, deep_b2, nullptr, mid2, tok, cnt);
    egemm_k<2><<<dim3(C_ / 128, N_ / 128, E_), 256, TG_SMEM>>>(
        h1, mid1, mid2, deep_w3, simple_w2, deep_b3, simple_b2, Yc, tok, cnt);

    // slot epilogue (exactly 2N active blocks) + final combine
    expert_epi_slots<<<2 * N_, 256>>>(Yc, h2, tok, gw, slot,
                                      deep_ln_g, deep_ln_b,
                                      simple_ln_g, simple_ln_b);
    combine_kernel<<<N_, 256>>>(Yc, slot, out);
}